// round 11
// baseline (speedup 1.0000x reference)
#include <cuda_runtime.h>
#include <cstdint>

#define NN 100000
#define NE 800000
#define NBLK 148
#define ET 448          // edge kernel threads (14 warps)

typedef unsigned long long u64;
typedef unsigned int u32;

// scratch (allocation-free rule: __device__ globals)
__device__ float g_agg[NN * 32];
__device__ float g_P[NN * 64];          // fragment-major: [n][q*16 + nt*2 + c]
__device__ float g_Q[NN * 64];
__device__ ulonglong2 g_Ball[2048];     // weight frags (B0 unused | B1 | B2), bf16 hi|lo
__device__ ulonglong2 g_BP[2048];       // precompute weight frags (P|Q halves)

// ---------------- packed fp32x2 helpers ----------------
__device__ __forceinline__ u64 pack2(float x) {
    u64 r; asm("mov.b64 %0, {%1, %1};" : "=l"(r) : "f"(x)); return r;
}
__device__ __forceinline__ u64 pack2f(float a, float b) {
    u64 r; asm("mov.b64 %0, {%1, %2};" : "=l"(r) : "f"(a), "f"(b)); return r;
}
__device__ __forceinline__ void unpack2(u64 v, float& a, float& b) {
    asm("mov.b64 {%0, %1}, %2;" : "=f"(a), "=f"(b) : "l"(v));
}
__device__ __forceinline__ void ffma2(u64& d, u64 a, u64 b) {
    asm("fma.rn.f32x2 %0, %1, %2, %0;" : "+l"(d) : "l"(a), "l"(b));
}
__device__ __forceinline__ void rank1_16(float xf, const float* w16, u64* a0) {
    u64 xa = pack2(xf);
    const ulonglong2* wr = (const ulonglong2*)w16;
#pragma unroll
    for (int j = 0; j < 4; j++) {
        ulonglong2 w = wr[j];
        ffma2(a0[2 * j],     xa, w.x);
        ffma2(a0[2 * j + 1], xa, w.y);
    }
}

// ---------------- bf16 emulation helpers ----------------
__device__ __forceinline__ u32 bf2pack(float x0, float x1) {
    u32 r;
    asm("cvt.rn.bf16x2.f32 %0, %1, %2;" : "=r"(r) : "f"(x1), "f"(x0));
    return r;
}
__device__ __forceinline__ void split_bf2(float x0, float x1, u32& h, u32& l) {
    h = bf2pack(x0, x1);
    float r0 = x0 - __uint_as_float(h << 16);
    float r1 = x1 - __uint_as_float(h & 0xFFFF0000u);
    l = bf2pack(r0, r1);
}
__device__ __forceinline__ void mma_bf(float c[4], const u32 a[4], u32 b0, u32 b1) {
    asm volatile(
        "mma.sync.aligned.m16n8k16.row.col.f32.bf16.bf16.f32 "
        "{%0,%1,%2,%3}, {%4,%5,%6,%7}, {%8,%9}, {%0,%1,%2,%3};"
        : "+f"(c[0]), "+f"(c[1]), "+f"(c[2]), "+f"(c[3])
        : "r"(a[0]), "r"(a[1]), "r"(a[2]), "r"(a[3]), "r"(b0), "r"(b1));
}
template <int NTC>
__device__ __forceinline__ void gemm_step(float C[][4], const u32 ah[4], const u32 al[4],
                                          const ulonglong2* sB, int kc, int Kc, int lane) {
    u32 bh[NTC][2], bl[NTC][2];
#pragma unroll
    for (int nt = 0; nt < NTC; nt++) {
        ulonglong2 t = sB[(nt * Kc + kc) * 32 + lane];
        bh[nt][0] = (u32)t.x; bl[nt][0] = (u32)(t.x >> 32);
        bh[nt][1] = (u32)t.y; bl[nt][1] = (u32)(t.y >> 32);
    }
#pragma unroll
    for (int nt = 0; nt < NTC; nt++) mma_bf(C[nt], ah, bh[nt][0], bh[nt][1]);
#pragma unroll
    for (int nt = 0; nt < NTC; nt++) mma_bf(C[nt], ah, bl[nt][0], bl[nt][1]);
#pragma unroll
    for (int nt = 0; nt < NTC; nt++) mma_bf(C[nt], al, bh[nt][0], bh[nt][1]);
}
// no memory clobber: lets next-tile gathers pipeline past the scatter
__device__ __forceinline__ void red2(float* p, float x, float y) {
    asm volatile("red.global.add.v2.f32 [%0], {%1,%2};" :: "l"(p), "f"(x), "f"(y));
}

// ---------------- setup: natural-order bf16 hi|lo weight fragments ----------------
__global__ void setup_kernel(const float* __restrict__ w0, const float* __restrict__ w1,
                             const float* __restrict__ w2) {
    int i = blockIdx.x * 256 + threadIdx.x;
    if (i >= 4096) return;
    int lane = i & 31, f = i >> 5;
    int g = lane >> 2, q = lane & 3;
    float v00, v01, v10, v11;
    if (f < 64) {
        const float* W; int nidx, k0, stride;
        if (f < 16)      { int nt = f >> 1,  kc = f & 1;  W = w0 + 128 * 64; stride = 64; nidx = nt * 8 + g; k0 = 16 * kc + 2 * q; }
        else if (f < 48) { int ff = f - 16; int nt = ff >> 2, kc = ff & 3; W = w1; stride = 64; nidx = nt * 8 + g; k0 = 16 * kc + 2 * q; }
        else             { int ff = f - 48; int nt = ff >> 2, kc = ff & 3; W = w2; stride = 32; nidx = nt * 8 + g; k0 = 16 * kc + 2 * q; }
        v00 = W[(size_t)k0 * stride + nidx];
        v01 = W[(size_t)(k0 + 1) * stride + nidx];
        v10 = W[(size_t)(k0 + 8) * stride + nidx];
        v11 = W[(size_t)(k0 + 9) * stride + nidx];
    } else {
        int ff = f - 64;
        int nt = ff >> 2, kc = ff & 3;
        int isq = (nt >= 8) ? 32 : 0;
        int nidx = (nt & 7) * 8 + g;
        int k0 = 16 * kc + 2 * q;
        int r00 = ((k0     < 32) ? k0     : k0 + 32) + isq;
        int r01 = ((k0 + 1 < 32) ? k0 + 1 : k0 + 33) + isq;
        int r10 = ((k0 + 8 < 32) ? k0 + 8 : k0 + 40) + isq;
        int r11 = ((k0 + 9 < 32) ? k0 + 9 : k0 + 41) + isq;
        v00 = w0[(size_t)r00 * 64 + nidx];
        v01 = w0[(size_t)r01 * 64 + nidx];
        v10 = w0[(size_t)r10 * 64 + nidx];
        v11 = w0[(size_t)r11 * 64 + nidx];
    }
    u32 h0, l0, h1, l1;
    split_bf2(v00, v01, h0, l0);
    split_bf2(v10, v11, h1, l1);
    ulonglong2 t;
    t.x = (u64)h0 | ((u64)l0 << 32);
    t.y = (u64)h1 | ((u64)l1 << 32);
    if (f < 64) g_Ball[i] = t; else g_BP[i - 2048] = t;
}

// ---------------- precompute: P|Q = [h_s|h_d] @ W' via bf16 MMA; zeros g_agg ----------------
__global__ void __launch_bounds__(256, 1)
pre_kernel(const float* __restrict__ h_s, const float* __restrict__ h_d,
           const float* __restrict__ b0) {
    extern __shared__ ulonglong2 smem_v2[];
    float* s_b0 = (float*)(smem_v2 + 2048);
    const int tid = threadIdx.x, wid = tid >> 5, lane = tid & 31;
    const int g = lane >> 2, q = lane & 3;
    for (int i = tid; i < 2048; i += 256) smem_v2[i] = g_BP[i];
    if (tid < 64) s_b0[tid] = b0[tid];
    __syncthreads();

    int n0 = (blockIdx.x * 8 + wid) * 16;
    if (n0 >= NN) return;

    float C[16][4];
#pragma unroll
    for (int nt = 0; nt < 8; nt++) {
        C[nt][0] = 0.f; C[nt][1] = 0.f; C[nt][2] = 0.f; C[nt][3] = 0.f;
        float b0v = s_b0[nt * 8 + 2 * q], b1v = s_b0[nt * 8 + 2 * q + 1];
        C[8 + nt][0] = b0v; C[8 + nt][1] = b1v; C[8 + nt][2] = b0v; C[8 + nt][3] = b1v;
    }
#pragma unroll
    for (int kc = 0; kc < 4; kc++) {
        const float* src = (kc < 2) ? h_s : h_d;
        int off = (kc & 1) * 16 + 2 * q;
        float2 x0 = *(const float2*)(src + (size_t)(n0 + g) * 32 + off);
        float2 x1 = *(const float2*)(src + (size_t)(n0 + 8 + g) * 32 + off);
        float2 x2 = *(const float2*)(src + (size_t)(n0 + g) * 32 + off + 8);
        float2 x3 = *(const float2*)(src + (size_t)(n0 + 8 + g) * 32 + off + 8);
        u32 ah[4], al[4];
        split_bf2(x0.x, x0.y, ah[0], al[0]);
        split_bf2(x1.x, x1.y, ah[1], al[1]);
        split_bf2(x2.x, x2.y, ah[2], al[2]);
        split_bf2(x3.x, x3.y, ah[3], al[3]);
        gemm_step<8>(C,     ah, al, smem_v2,           kc, 4, lane);   // P
        gemm_step<8>(C + 8, ah, al, smem_v2 + 32 * 32, kc, 4, lane);   // Q
    }
    // store fragment-major: [n][q*16 + nt*2]
#pragma unroll
    for (int j = 0; j < 4; j++) {
        *(float4*)(g_P + (size_t)(n0 + g)     * 64 + q * 16 + 4 * j) =
            make_float4(C[2*j][0], C[2*j][1], C[2*j+1][0], C[2*j+1][1]);
        *(float4*)(g_P + (size_t)(n0 + 8 + g) * 64 + q * 16 + 4 * j) =
            make_float4(C[2*j][2], C[2*j][3], C[2*j+1][2], C[2*j+1][3]);
        *(float4*)(g_Q + (size_t)(n0 + g)     * 64 + q * 16 + 4 * j) =
            make_float4(C[8+2*j][0], C[8+2*j][1], C[8+2*j+1][0], C[8+2*j+1][1]);
        *(float4*)(g_Q + (size_t)(n0 + 8 + g) * 64 + q * 16 + 4 * j) =
            make_float4(C[8+2*j][2], C[8+2*j][3], C[8+2*j+1][2], C[8+2*j+1][3]);
    }
    float4 z = make_float4(0.f, 0.f, 0.f, 0.f);
    float4* ag = (float4*)(g_agg + (size_t)n0 * 32);
#pragma unroll
    for (int i = 0; i < 4; i++) ag[lane + 32 * i] = z;
}

// ---------------- edge kernel: L0 on FFMA2 pipe, L1/L2 on tensor pipe ----------------
// smem (ulonglong2 units): sB1 [0,1024), sB2 [1024,1536), then
//   s_w0 (1024 u64 = 512 u2) [1536,2048), biases after.
#define SMEM_BYTES (2048 * 16 + 96 * 4)

__global__ void __launch_bounds__(ET, 1)
edge_kernel(const float* __restrict__ h_d, const float* __restrict__ ef,
            const int* __restrict__ si, const int* __restrict__ ri,
            const float* __restrict__ w0,
            const float* __restrict__ b1, const float* __restrict__ b2) {
    extern __shared__ ulonglong2 smem_v2[];
    ulonglong2* sB1 = smem_v2;           // 32 frags (L1)
    ulonglong2* sB2 = smem_v2 + 1024;    // 16 frags (L2)
    u64* s_w0 = (u64*)(smem_v2 + 1536);  // [q][k][nt] packed W0e col-pairs
    float* s_b1 = (float*)(smem_v2 + 2048);
    float* s_b2 = s_b1 + 64;

    const int tid = threadIdx.x, wid = tid >> 5, lane = tid & 31;
    // B1/B2 fragments (skip unused B0 frags at g_Ball[0..511])
    for (int i = tid; i < 1536; i += ET) smem_v2[i] = g_Ball[512 + i];
    // W0e packed: index i = q*256 + k*8 + nt -> (W0e[k][8nt+2q], [.. +1])
    for (int i = tid; i < 1024; i += ET) {
        int qq = i >> 8, k = (i >> 3) & 31, nt = i & 7;
        int c = 8 * nt + 2 * qq;
        const float* wr = w0 + (size_t)(128 + k) * 64 + c;
        ((float2*)s_w0)[i] = make_float2(wr[0], wr[1]);
    }
    if (tid < 64) s_b1[tid] = b1[tid];
    if (tid < 32) s_b2[tid] = b2[tid];
    __syncthreads();

    const int g = lane >> 2, q = lane & 3;
    const int col2 = 2 * q;
    const int WPC = ET / 32;
    const u64* s_w0q = s_w0 + q * 256;

#pragma unroll 1
    for (int base = blockIdx.x * (WPC * 16) + wid * 16; base < NE; base += NBLK * (WPC * 16)) {
        int e0 = base + g, e1 = base + 8 + g;
        bool v0 = e0 < NE, v1 = e1 < NE;
        int e0c = v0 ? e0 : NE - 1;
        int e1c = v1 ? e1 : NE - 1;
        int s0 = si[e0c], rc0 = ri[e0c];
        int s1 = si[e1c], rc1 = ri[e1c];

        // ===== layer 0 init: acc = P[s] + Q[r]  (packed f32x2, fragment-major) =====
        u64 ar0[8], ar1[8];
        {
            const float4* P0 = (const float4*)(g_P + (size_t)s0  * 64 + q * 16);
            const float4* Q0 = (const float4*)(g_Q + (size_t)rc0 * 64 + q * 16);
            const float4* P1 = (const float4*)(g_P + (size_t)s1  * 64 + q * 16);
            const float4* Q1 = (const float4*)(g_Q + (size_t)rc1 * 64 + q * 16);
#pragma unroll
            for (int j = 0; j < 4; j++) {
                float4 p = P0[j], qq = Q0[j];
                ar0[2*j]   = pack2f(p.x + qq.x, p.y + qq.y);
                ar0[2*j+1] = pack2f(p.z + qq.z, p.w + qq.w);
                p = P1[j]; qq = Q1[j];
                ar1[2*j]   = pack2f(p.x + qq.x, p.y + qq.y);
                ar1[2*j+1] = pack2f(p.z + qq.z, p.w + qq.w);
            }
        }
        // ===== layer 0: += ef @ W0e, exact fp32 on the fma pipe =====
        {
            const float4* E0 = (const float4*)(ef + (size_t)e0c * 32);
            const float4* E1 = (const float4*)(ef + (size_t)e1c * 32);
#pragma unroll 2
            for (int kb = 0; kb < 8; kb++) {
                float4 x0 = E0[kb], x1 = E1[kb];
                const ulonglong2* w4 = (const ulonglong2*)(s_w0q + kb * 32);
#pragma unroll
                for (int d = 0; d < 4; d++) {
                    float xs0 = (d == 0) ? x0.x : (d == 1) ? x0.y : (d == 2) ? x0.z : x0.w;
                    float xs1 = (d == 0) ? x1.x : (d == 1) ? x1.y : (d == 2) ? x1.z : x1.w;
                    u64 a0 = pack2(xs0), a1 = pack2(xs1);
                    ulonglong2 wa = w4[d*4+0], wb = w4[d*4+1];
                    ulonglong2 wc = w4[d*4+2], wd = w4[d*4+3];
                    ffma2(ar0[0], a0, wa.x); ffma2(ar0[1], a0, wa.y);
                    ffma2(ar0[2], a0, wb.x); ffma2(ar0[3], a0, wb.y);
                    ffma2(ar0[4], a0, wc.x); ffma2(ar0[5], a0, wc.y);
                    ffma2(ar0[6], a0, wd.x); ffma2(ar0[7], a0, wd.y);
                    ffma2(ar1[0], a1, wa.x); ffma2(ar1[1], a1, wa.y);
                    ffma2(ar1[2], a1, wb.x); ffma2(ar1[3], a1, wb.y);
                    ffma2(ar1[4], a1, wc.x); ffma2(ar1[5], a1, wc.y);
                    ffma2(ar1[6], a1, wd.x); ffma2(ar1[7], a1, wd.y);
                }
            }
        }

        // ===== layer 1 (tensor): A chained from ar (relu+split) =====
        float C1[8][4];
#pragma unroll
        for (int nt = 0; nt < 8; nt++) {
            float bb0 = s_b1[nt * 8 + col2], bb1 = s_b1[nt * 8 + col2 + 1];
            C1[nt][0] = bb0; C1[nt][1] = bb1; C1[nt][2] = bb0; C1[nt][3] = bb1;
        }
#pragma unroll
        for (int kc = 0; kc < 4; kc++) {
            u32 ah[4], al[4];
            float x, y;
            unpack2(ar0[2*kc],   x, y); split_bf2(fmaxf(x,0.f), fmaxf(y,0.f), ah[0], al[0]);
            unpack2(ar1[2*kc],   x, y); split_bf2(fmaxf(x,0.f), fmaxf(y,0.f), ah[1], al[1]);
            unpack2(ar0[2*kc+1], x, y); split_bf2(fmaxf(x,0.f), fmaxf(y,0.f), ah[2], al[2]);
            unpack2(ar1[2*kc+1], x, y); split_bf2(fmaxf(x,0.f), fmaxf(y,0.f), ah[3], al[3]);
            gemm_step<8>(C1, ah, al, sB1, kc, 4, lane);
        }

        // ===== layer 2 (tensor) =====
        float C2[4][4];
#pragma unroll
        for (int nt = 0; nt < 4; nt++) {
            float bb0 = s_b2[nt * 8 + col2], bb1 = s_b2[nt * 8 + col2 + 1];
            C2[nt][0] = bb0; C2[nt][1] = bb1; C2[nt][2] = bb0; C2[nt][3] = bb1;
        }
#pragma unroll
        for (int kc = 0; kc < 4; kc++) {
            u32 ah[4], al[4];
            split_bf2(fmaxf(C1[2*kc][0], 0.f), fmaxf(C1[2*kc][1], 0.f), ah[0], al[0]);
            split_bf2(fmaxf(C1[2*kc][2], 0.f), fmaxf(C1[2*kc][3], 0.f), ah[1], al[1]);
            split_bf2(fmaxf(C1[2*kc+1][0], 0.f), fmaxf(C1[2*kc+1][1], 0.f), ah[2], al[2]);
            split_bf2(fmaxf(C1[2*kc+1][2], 0.f), fmaxf(C1[2*kc+1][3], 0.f), ah[3], al[3]);
            gemm_step<4>(C2, ah, al, sB2, kc, 4, lane);
        }

        // ===== epilogue: relu(psi) * (h_dj - h_di), vector scatter-add =====
#pragma unroll
        for (int nt = 0; nt < 4; nt++) {
            int cc = nt * 8 + col2;
            if (v0) {
                float2 dj = *(const float2*)(h_d + (size_t)rc0 * 32 + cc);
                float2 di = *(const float2*)(h_d + (size_t)s0 * 32 + cc);
                red2(g_agg + (size_t)rc0 * 32 + cc,
                     fmaxf(C2[nt][0], 0.f) * (dj.x - di.x),
                     fmaxf(C2[nt][1], 0.f) * (dj.y - di.y));
            }
            if (v1) {
                float2 dj = *(const float2*)(h_d + (size_t)rc1 * 32 + cc);
                float2 di = *(const float2*)(h_d + (size_t)s1 * 32 + cc);
                red2(g_agg + (size_t)rc1 * 32 + cc,
                     fmaxf(C2[nt][2], 0.f) * (dj.x - di.x),
                     fmaxf(C2[nt][3], 0.f) * (dj.y - di.y));
            }
        }
    }
}

// out[n] = h_d_prev[n] + agg[n] @ W   (2 threads per node, 16 outputs each)
__global__ void __launch_bounds__(256)
final_kernel(const float* __restrict__ h_d, const float* __restrict__ W,
             float* __restrict__ out) {
    __shared__ float sW[1024];
    int tid = threadIdx.x;
    {
        float4* d4 = (float4*)sW;
        const float4* s4 = (const float4*)W;
        for (int i = tid; i < 256; i += 256) d4[i] = s4[i];
    }
    __syncthreads();
    int idx = blockIdx.x * 256 + tid;
    int n = idx >> 1, half = idx & 1;
    if (n >= NN) return;

    u64 acc[8];
    {
        const ulonglong2* hp = (const ulonglong2*)(h_d + (size_t)n * 32 + half * 16);
#pragma unroll
        for (int j = 0; j < 4; j++) {
            ulonglong2 t = hp[j];
            acc[2 * j] = t.x; acc[2 * j + 1] = t.y;
        }
    }
    const float4* ap = (const float4*)(g_agg + (size_t)n * 32);
    const float* wb = sW + half * 16;
#pragma unroll
    for (int i = 0; i < 8; i++) {
        float4 a = ap[i];
        rank1_16(a.x, wb + (4 * i) * 32,     acc);
        rank1_16(a.y, wb + (4 * i + 1) * 32, acc);
        rank1_16(a.z, wb + (4 * i + 2) * 32, acc);
        rank1_16(a.w, wb + (4 * i + 3) * 32, acc);
    }
    ulonglong2* op = (ulonglong2*)(out + (size_t)n * 32 + half * 16);
#pragma unroll
    for (int j = 0; j < 4; j++) {
        ulonglong2 t; t.x = acc[2 * j]; t.y = acc[2 * j + 1];
        op[j] = t;
    }
}

extern "C" void kernel_launch(void* const* d_in, const int* in_sizes, int n_in,
                              void* d_out, int out_size) {
    const float* h_d = (const float*)d_in[0];
    const float* h_s = (const float*)d_in[1];
    const float* ef  = (const float*)d_in[2];
    const int*   si  = (const int*)d_in[3];
    const int*   ri  = (const int*)d_in[4];
    const float* w0  = (const float*)d_in[5];
    const float* b0  = (const float*)d_in[6];
    const float* w1  = (const float*)d_in[7];
    const float* b1  = (const float*)d_in[8];
    const float* w2  = (const float*)d_in[9];
    const float* b2  = (const float*)d_in[10];
    const float* W   = (const float*)d_in[11];
    float* out = (float*)d_out;

    cudaFuncSetAttribute(edge_kernel, cudaFuncAttributeMaxDynamicSharedMemorySize,
                         SMEM_BYTES);
    cudaFuncSetAttribute(pre_kernel, cudaFuncAttributeMaxDynamicSharedMemorySize,
                         2048 * 16 + 64 * 4);

    setup_kernel<<<16, 256>>>(w0, w1, w2);
    pre_kernel<<<782, 256, 2048 * 16 + 64 * 4>>>(h_s, h_d, b0);
    edge_kernel<<<NBLK, ET, SMEM_BYTES>>>(h_d, ef, si, ri, w0, b1, b2);
    final_kernel<<<(2 * NN + 255) / 256, 256>>>(h_d, W, out);
}

// round 12
// speedup vs baseline: 2.6852x; 2.6852x over previous
#include <cuda_runtime.h>
#include <cuda_fp16.h>
#include <cstdint>

#define NN 100000
#define NE 800000
#define NBLK 148
#define ET 448          // edge kernel threads (14 warps)

typedef unsigned long long u64;
typedef unsigned int u32;

// scratch (allocation-free rule: __device__ globals)
__device__ float g_agg[NN * 32];
__device__ float g_P[NN * 64];          // fragment-major: [n][q*16 + nt*2 + c]
__device__ float g_Q[NN * 64];
__device__ ulonglong2 g_Ball[2048];     // edge weight frags (B0|B1|B2), fp16 hi|lo
__device__ ulonglong2 g_BP[2048];       // precompute weight frags (P|Q halves), bf16 hi|lo

// ---------------- packed fp32x2 helpers (final kernel) ----------------
__device__ __forceinline__ u64 pack2(float x) {
    u64 r; asm("mov.b64 %0, {%1, %1};" : "=l"(r) : "f"(x)); return r;
}
__device__ __forceinline__ void ffma2(u64& d, u64 a, u64 b) {
    asm("fma.rn.f32x2 %0, %1, %2, %0;" : "+l"(d) : "l"(a), "l"(b));
}
__device__ __forceinline__ void rank1_16(float xf, const float* w16, u64* a0) {
    u64 xa = pack2(xf);
    const ulonglong2* wr = (const ulonglong2*)w16;
#pragma unroll
    for (int j = 0; j < 4; j++) {
        ulonglong2 w = wr[j];
        ffma2(a0[2 * j],     xa, w.x);
        ffma2(a0[2 * j + 1], xa, w.y);
    }
}

// ---------------- bf16 emulation helpers (pre_kernel path) ----------------
__device__ __forceinline__ u32 bf2pack(float x0, float x1) {
    u32 r;
    asm("cvt.rn.bf16x2.f32 %0, %1, %2;" : "=r"(r) : "f"(x1), "f"(x0));
    return r;
}
__device__ __forceinline__ void split_bf2(float x0, float x1, u32& h, u32& l) {
    h = bf2pack(x0, x1);
    float r0 = x0 - __uint_as_float(h << 16);
    float r1 = x1 - __uint_as_float(h & 0xFFFF0000u);
    l = bf2pack(r0, r1);
}
__device__ __forceinline__ void mma_bf(float c[4], const u32 a[4], u32 b0, u32 b1) {
    asm volatile(
        "mma.sync.aligned.m16n8k16.row.col.f32.bf16.bf16.f32 "
        "{%0,%1,%2,%3}, {%4,%5,%6,%7}, {%8,%9}, {%0,%1,%2,%3};"
        : "+f"(c[0]), "+f"(c[1]), "+f"(c[2]), "+f"(c[3])
        : "r"(a[0]), "r"(a[1]), "r"(a[2]), "r"(a[3]), "r"(b0), "r"(b1));
}
template <int NTC>
__device__ __forceinline__ void gemm_step_bf(float C[][4], const u32 ah[4], const u32 al[4],
                                             const ulonglong2* sB, int kc, int Kc, int lane) {
    u32 bh[NTC][2], bl[NTC][2];
#pragma unroll
    for (int nt = 0; nt < NTC; nt++) {
        ulonglong2 t = sB[(nt * Kc + kc) * 32 + lane];
        bh[nt][0] = (u32)t.x; bl[nt][0] = (u32)(t.x >> 32);
        bh[nt][1] = (u32)t.y; bl[nt][1] = (u32)(t.y >> 32);
    }
#pragma unroll
    for (int nt = 0; nt < NTC; nt++) mma_bf(C[nt], ah, bh[nt][0], bh[nt][1]);
#pragma unroll
    for (int nt = 0; nt < NTC; nt++) mma_bf(C[nt], ah, bl[nt][0], bl[nt][1]);
#pragma unroll
    for (int nt = 0; nt < NTC; nt++) mma_bf(C[nt], al, bh[nt][0], bh[nt][1]);
}

// ---------------- fp16 2-term helpers (edge kernel path) ----------------
__device__ __forceinline__ u32 f16pack(float x0, float x1) {
    u32 r;
    asm("cvt.rn.f16x2.f32 %0, %1, %2;" : "=r"(r) : "f"(x1), "f"(x0));   // low = x0
    return r;
}
__device__ __forceinline__ void mma_f16(float c[4], const u32 a[4], u32 b0, u32 b1) {
    asm volatile(
        "mma.sync.aligned.m16n8k16.row.col.f32.f16.f16.f32 "
        "{%0,%1,%2,%3}, {%4,%5,%6,%7}, {%8,%9}, {%0,%1,%2,%3};"
        : "+f"(c[0]), "+f"(c[1]), "+f"(c[2]), "+f"(c[3])
        : "r"(a[0]), "r"(a[1]), "r"(a[2]), "r"(a[3]), "r"(b0), "r"(b1));
}
// 2-term K-chunk: C += A*Bh + A*Bl  (A single fp16, B split at setup)
template <int NTC>
__device__ __forceinline__ void gemm_step(float C[][4], const u32 a[4],
                                          const ulonglong2* sB, int kc, int Kc, int lane) {
    u32 bh[NTC][2], bl[NTC][2];
#pragma unroll
    for (int nt = 0; nt < NTC; nt++) {
        ulonglong2 t = sB[(nt * Kc + kc) * 32 + lane];
        bh[nt][0] = (u32)t.x; bl[nt][0] = (u32)(t.x >> 32);
        bh[nt][1] = (u32)t.y; bl[nt][1] = (u32)(t.y >> 32);
    }
#pragma unroll
    for (int nt = 0; nt < NTC; nt++) mma_f16(C[nt], a, bh[nt][0], bh[nt][1]);
#pragma unroll
    for (int nt = 0; nt < NTC; nt++) mma_f16(C[nt], a, bl[nt][0], bl[nt][1]);
}
__device__ __forceinline__ void build_a(const float cA[4], const float cB[4], u32 a[4]) {
    a[0] = f16pack(fmaxf(cA[0], 0.f), fmaxf(cA[1], 0.f));
    a[1] = f16pack(fmaxf(cA[2], 0.f), fmaxf(cA[3], 0.f));
    a[2] = f16pack(fmaxf(cB[0], 0.f), fmaxf(cB[1], 0.f));
    a[3] = f16pack(fmaxf(cB[2], 0.f), fmaxf(cB[3], 0.f));
}
__device__ __forceinline__ void red2(float* p, float x, float y) {
    asm volatile("red.global.add.v2.f32 [%0], {%1,%2};" :: "l"(p), "f"(x), "f"(y));
}
// fp16 split: v = h + l, h/l pair-packed
__device__ __forceinline__ void split_f16(float x0, float x1, u32& h, u32& l) {
    __half h0 = __float2half_rn(x0), h1 = __float2half_rn(x1);
    float r0 = x0 - __half2float(h0);
    float r1 = x1 - __half2float(h1);
    __half l0 = __float2half_rn(r0), l1 = __float2half_rn(r1);
    h = ((u32)__half_as_ushort(h1) << 16) | __half_as_ushort(h0);
    l = ((u32)__half_as_ushort(l1) << 16) | __half_as_ushort(l0);
}

// ---------------- setup: edge frags fp16 hi|lo, pre frags bf16 hi|lo ----------------
__global__ void setup_kernel(const float* __restrict__ w0, const float* __restrict__ w1,
                             const float* __restrict__ w2) {
    int i = blockIdx.x * 256 + threadIdx.x;
    if (i >= 4096) return;
    int lane = i & 31, f = i >> 5;
    int g = lane >> 2, q = lane & 3;
    float v00, v01, v10, v11;
    if (f < 64) {
        const float* W; int nidx, k0, stride;
        if (f < 16)      { int nt = f >> 1,  kc = f & 1;  W = w0 + 128 * 64; stride = 64; nidx = nt * 8 + g; k0 = 16 * kc + 2 * q; }
        else if (f < 48) { int ff = f - 16; int nt = ff >> 2, kc = ff & 3; W = w1; stride = 64; nidx = nt * 8 + g; k0 = 16 * kc + 2 * q; }
        else             { int ff = f - 48; int nt = ff >> 2, kc = ff & 3; W = w2; stride = 32; nidx = nt * 8 + g; k0 = 16 * kc + 2 * q; }
        v00 = W[(size_t)k0 * stride + nidx];
        v01 = W[(size_t)(k0 + 1) * stride + nidx];
        v10 = W[(size_t)(k0 + 8) * stride + nidx];
        v11 = W[(size_t)(k0 + 9) * stride + nidx];
        u32 h0, l0, h1, l1;
        split_f16(v00, v01, h0, l0);
        split_f16(v10, v11, h1, l1);
        ulonglong2 t;
        t.x = (u64)h0 | ((u64)l0 << 32);
        t.y = (u64)h1 | ((u64)l1 << 32);
        g_Ball[i] = t;
    } else {
        int ff = f - 64;
        int nt = ff >> 2, kc = ff & 3;
        int isq = (nt >= 8) ? 32 : 0;
        int nidx = (nt & 7) * 8 + g;
        int k0 = 16 * kc + 2 * q;
        int r00 = ((k0     < 32) ? k0     : k0 + 32) + isq;
        int r01 = ((k0 + 1 < 32) ? k0 + 1 : k0 + 33) + isq;
        int r10 = ((k0 + 8 < 32) ? k0 + 8 : k0 + 40) + isq;
        int r11 = ((k0 + 9 < 32) ? k0 + 9 : k0 + 41) + isq;
        v00 = w0[(size_t)r00 * 64 + nidx];
        v01 = w0[(size_t)r01 * 64 + nidx];
        v10 = w0[(size_t)r10 * 64 + nidx];
        v11 = w0[(size_t)r11 * 64 + nidx];
        u32 h0, l0, h1, l1;
        split_bf2(v00, v01, h0, l0);
        split_bf2(v10, v11, h1, l1);
        ulonglong2 t;
        t.x = (u64)h0 | ((u64)l0 << 32);
        t.y = (u64)h1 | ((u64)l1 << 32);
        g_BP[i - 2048] = t;
    }
}

// ---------------- precompute: P|Q = [h_s|h_d] @ W' via bf16-3term MMA; zeros g_agg ----------------
__global__ void __launch_bounds__(256, 1)
pre_kernel(const float* __restrict__ h_s, const float* __restrict__ h_d,
           const float* __restrict__ b0) {
    extern __shared__ ulonglong2 smem_v2[];
    float* s_b0 = (float*)(smem_v2 + 2048);
    const int tid = threadIdx.x, wid = tid >> 5, lane = tid & 31;
    const int g = lane >> 2, q = lane & 3;
    for (int i = tid; i < 2048; i += 256) smem_v2[i] = g_BP[i];
    if (tid < 64) s_b0[tid] = b0[tid];
    __syncthreads();

    int n0 = (blockIdx.x * 8 + wid) * 16;
    if (n0 >= NN) return;

    float C[16][4];
#pragma unroll
    for (int nt = 0; nt < 8; nt++) {
        C[nt][0] = 0.f; C[nt][1] = 0.f; C[nt][2] = 0.f; C[nt][3] = 0.f;
        float b0v = s_b0[nt * 8 + 2 * q], b1v = s_b0[nt * 8 + 2 * q + 1];
        C[8 + nt][0] = b0v; C[8 + nt][1] = b1v; C[8 + nt][2] = b0v; C[8 + nt][3] = b1v;
    }
#pragma unroll
    for (int kc = 0; kc < 4; kc++) {
        const float* src = (kc < 2) ? h_s : h_d;
        int off = (kc & 1) * 16 + 2 * q;
        float2 x0 = *(const float2*)(src + (size_t)(n0 + g) * 32 + off);
        float2 x1 = *(const float2*)(src + (size_t)(n0 + 8 + g) * 32 + off);
        float2 x2 = *(const float2*)(src + (size_t)(n0 + g) * 32 + off + 8);
        float2 x3 = *(const float2*)(src + (size_t)(n0 + 8 + g) * 32 + off + 8);
        u32 ah[4], al[4];
        split_bf2(x0.x, x0.y, ah[0], al[0]);
        split_bf2(x1.x, x1.y, ah[1], al[1]);
        split_bf2(x2.x, x2.y, ah[2], al[2]);
        split_bf2(x3.x, x3.y, ah[3], al[3]);
        gemm_step_bf<8>(C,     ah, al, smem_v2,           kc, 4, lane);   // P
        gemm_step_bf<8>(C + 8, ah, al, smem_v2 + 32 * 32, kc, 4, lane);   // Q
    }
    // store fragment-major: [n][q*16 + nt*2]
#pragma unroll
    for (int j = 0; j < 4; j++) {
        *(float4*)(g_P + (size_t)(n0 + g)     * 64 + q * 16 + 4 * j) =
            make_float4(C[2*j][0], C[2*j][1], C[2*j+1][0], C[2*j+1][1]);
        *(float4*)(g_P + (size_t)(n0 + 8 + g) * 64 + q * 16 + 4 * j) =
            make_float4(C[2*j][2], C[2*j][3], C[2*j+1][2], C[2*j+1][3]);
        *(float4*)(g_Q + (size_t)(n0 + g)     * 64 + q * 16 + 4 * j) =
            make_float4(C[8+2*j][0], C[8+2*j][1], C[8+2*j+1][0], C[8+2*j+1][1]);
        *(float4*)(g_Q + (size_t)(n0 + 8 + g) * 64 + q * 16 + 4 * j) =
            make_float4(C[8+2*j][2], C[8+2*j][3], C[8+2*j+1][2], C[8+2*j+1][3]);
    }
    float4 z = make_float4(0.f, 0.f, 0.f, 0.f);
    float4* ag = (float4*)(g_agg + (size_t)n0 * 32);
#pragma unroll
    for (int i = 0; i < 4; i++) ag[lane + 32 * i] = z;
}

// ---------------- edge kernel: fp16 2-term MMA MLP ----------------
#define SMEM_BYTES (2048 * 16 + 96 * 4)

__global__ void __launch_bounds__(ET, 1)
edge_kernel(const float* __restrict__ h_d, const float* __restrict__ ef,
            const int* __restrict__ si, const int* __restrict__ ri,
            const float* __restrict__ b1, const float* __restrict__ b2) {
    extern __shared__ ulonglong2 smem_v2[];
    ulonglong2* sB0 = smem_v2;           // 16 frags
    ulonglong2* sB1 = smem_v2 + 512;     // 32 frags
    ulonglong2* sB2 = smem_v2 + 1536;    // 16 frags
    float* s_b1 = (float*)(smem_v2 + 2048);
    float* s_b2 = s_b1 + 64;

    const int tid = threadIdx.x, wid = tid >> 5, lane = tid & 31;
    for (int i = tid; i < 2048; i += ET) smem_v2[i] = g_Ball[i];
    if (tid < 64) s_b1[tid] = b1[tid];
    if (tid < 32) s_b2[tid] = b2[tid];
    __syncthreads();

    const int g = lane >> 2, q = lane & 3;
    const int col2 = 2 * q;
    const int WPC = ET / 32;

#pragma unroll 1
    for (int base = blockIdx.x * (WPC * 16) + wid * 16; base < NE; base += NBLK * (WPC * 16)) {
        int e0 = base + g, e1 = base + 8 + g;
        bool v0 = e0 < NE, v1 = e1 < NE;
        int e0c = v0 ? e0 : NE - 1;
        int e1c = v1 ? e1 : NE - 1;
        int s0 = si[e0c], rc0 = ri[e0c];
        int s1 = si[e1c], rc1 = ri[e1c];

        // ===== layer 0: C init from P[s]+Q[r] (exact fp32) =====
        float C[8][4];
        {
            const float4* P0 = (const float4*)(g_P + (size_t)s0  * 64 + q * 16);
            const float4* Q0 = (const float4*)(g_Q + (size_t)rc0 * 64 + q * 16);
            const float4* P1 = (const float4*)(g_P + (size_t)s1  * 64 + q * 16);
            const float4* Q1 = (const float4*)(g_Q + (size_t)rc1 * 64 + q * 16);
#pragma unroll
            for (int j = 0; j < 4; j++) {
                float4 p = P0[j], qq = Q0[j];
                C[2*j][0]   = p.x + qq.x; C[2*j][1]   = p.y + qq.y;
                C[2*j+1][0] = p.z + qq.z; C[2*j+1][1] = p.w + qq.w;
                p = P1[j]; qq = Q1[j];
                C[2*j][2]   = p.x + qq.x; C[2*j][3]   = p.y + qq.y;
                C[2*j+1][2] = p.z + qq.z; C[2*j+1][3] = p.w + qq.w;
            }
        }
        // ===== layer 0: += ef @ W0e (fp16 A, split B) =====
#pragma unroll
        for (int kc = 0; kc < 2; kc++) {
            int off = 16 * kc + col2;
            float2 x0 = *(const float2*)(ef + (size_t)e0c * 32 + off);
            float2 x1 = *(const float2*)(ef + (size_t)e1c * 32 + off);
            float2 x2 = *(const float2*)(ef + (size_t)e0c * 32 + off + 8);
            float2 x3 = *(const float2*)(ef + (size_t)e1c * 32 + off + 8);
            u32 a[4];
            a[0] = f16pack(x0.x, x0.y);
            a[1] = f16pack(x1.x, x1.y);
            a[2] = f16pack(x2.x, x2.y);
            a[3] = f16pack(x3.x, x3.y);
            gemm_step<8>(C, a, sB0, kc, 2, lane);
        }

        // ===== layer 1 =====
        float C1[8][4];
#pragma unroll
        for (int nt = 0; nt < 8; nt++) {
            float bb0 = s_b1[nt * 8 + col2], bb1 = s_b1[nt * 8 + col2 + 1];
            C1[nt][0] = bb0; C1[nt][1] = bb1; C1[nt][2] = bb0; C1[nt][3] = bb1;
        }
#pragma unroll
        for (int kc = 0; kc < 4; kc++) {
            u32 a[4];
            build_a(C[2 * kc], C[2 * kc + 1], a);
            gemm_step<8>(C1, a, sB1, kc, 4, lane);
        }

        // ===== layer 2 =====
        float C2[4][4];
#pragma unroll
        for (int nt = 0; nt < 4; nt++) {
            float bb0 = s_b2[nt * 8 + col2], bb1 = s_b2[nt * 8 + col2 + 1];
            C2[nt][0] = bb0; C2[nt][1] = bb1; C2[nt][2] = bb0; C2[nt][3] = bb1;
        }
#pragma unroll
        for (int kc = 0; kc < 4; kc++) {
            u32 a[4];
            build_a(C1[2 * kc], C1[2 * kc + 1], a);
            gemm_step<4>(C2, a, sB2, kc, 4, lane);
        }

        // ===== epilogue: relu(psi) * (h_dj - h_di), vector scatter-add =====
#pragma unroll
        for (int nt = 0; nt < 4; nt++) {
            int cc = nt * 8 + col2;
            if (v0) {
                float2 dj = *(const float2*)(h_d + (size_t)rc0 * 32 + cc);
                float2 di = *(const float2*)(h_d + (size_t)s0 * 32 + cc);
                red2(g_agg + (size_t)rc0 * 32 + cc,
                     fmaxf(C2[nt][0], 0.f) * (dj.x - di.x),
                     fmaxf(C2[nt][1], 0.f) * (dj.y - di.y));
            }
            if (v1) {
                float2 dj = *(const float2*)(h_d + (size_t)rc1 * 32 + cc);
                float2 di = *(const float2*)(h_d + (size_t)s1 * 32 + cc);
                red2(g_agg + (size_t)rc1 * 32 + cc,
                     fmaxf(C2[nt][2], 0.f) * (dj.x - di.x),
                     fmaxf(C2[nt][3], 0.f) * (dj.y - di.y));
            }
        }
    }
}

// out[n] = h_d_prev[n] + agg[n] @ W   (2 threads per node, 16 outputs each)
__global__ void __launch_bounds__(256)
final_kernel(const float* __restrict__ h_d, const float* __restrict__ W,
             float* __restrict__ out) {
    __shared__ float sW[1024];
    int tid = threadIdx.x;
    {
        float4* d4 = (float4*)sW;
        const float4* s4 = (const float4*)W;
        for (int i = tid; i < 256; i += 256) d4[i] = s4[i];
    }
    __syncthreads();
    int idx = blockIdx.x * 256 + tid;
    int n = idx >> 1, half = idx & 1;
    if (n >= NN) return;

    u64 acc[8];
    {
        const ulonglong2* hp = (const ulonglong2*)(h_d + (size_t)n * 32 + half * 16);
#pragma unroll
        for (int j = 0; j < 4; j++) {
            ulonglong2 t = hp[j];
            acc[2 * j] = t.x; acc[2 * j + 1] = t.y;
        }
    }
    const float4* ap = (const float4*)(g_agg + (size_t)n * 32);
    const float* wb = sW + half * 16;
#pragma unroll
    for (int i = 0; i < 8; i++) {
        float4 a = ap[i];
        rank1_16(a.x, wb + (4 * i) * 32,     acc);
        rank1_16(a.y, wb + (4 * i + 1) * 32, acc);
        rank1_16(a.z, wb + (4 * i + 2) * 32, acc);
        rank1_16(a.w, wb + (4 * i + 3) * 32, acc);
    }
    ulonglong2* op = (ulonglong2*)(out + (size_t)n * 32 + half * 16);
#pragma unroll
    for (int j = 0; j < 4; j++) {
        ulonglong2 t; t.x = acc[2 * j]; t.y = acc[2 * j + 1];
        op[j] = t;
    }
}

extern "C" void kernel_launch(void* const* d_in, const int* in_sizes, int n_in,
                              void* d_out, int out_size) {
    const float* h_d = (const float*)d_in[0];
    const float* h_s = (const float*)d_in[1];
    const float* ef  = (const float*)d_in[2];
    const int*   si  = (const int*)d_in[3];
    const int*   ri  = (const int*)d_in[4];
    const float* w0  = (const float*)d_in[5];
    const float* b0  = (const float*)d_in[6];
    const float* w1  = (const float*)d_in[7];
    const float* b1  = (const float*)d_in[8];
    const float* w2  = (const float*)d_in[9];
    const float* b2  = (const float*)d_in[10];
    const float* W   = (const float*)d_in[11];
    float* out = (float*)d_out;

    cudaFuncSetAttribute(edge_kernel, cudaFuncAttributeMaxDynamicSharedMemorySize,
                         SMEM_BYTES);
    cudaFuncSetAttribute(pre_kernel, cudaFuncAttributeMaxDynamicSharedMemorySize,
                         2048 * 16 + 64 * 4);

    setup_kernel<<<16, 256>>>(w0, w1, w2);
    pre_kernel<<<782, 256, 2048 * 16 + 64 * 4>>>(h_s, h_d, b0);
    edge_kernel<<<NBLK, ET, SMEM_BYTES>>>(h_d, ef, si, ri, b1, b2);
    final_kernel<<<(2 * NN + 255) / 256, 256>>>(h_d, W, out);
}

// round 13
// speedup vs baseline: 2.8123x; 1.0473x over previous
#include <cuda_runtime.h>
#include <cuda_fp16.h>
#include <cstdint>

#define NN 100000
#define NE 800000
#define NBLK 148
#define ET 448          // edge kernel threads (14 warps)

typedef unsigned long long u64;
typedef unsigned int u32;

// scratch (allocation-free rule: __device__ globals)
__device__ float g_agg[NN * 32];
__device__ float g_P[NN * 64];          // fragment-major: [n][q*16 + nt*2 + c]
__device__ float g_Q[NN * 64];
__device__ u64 g_B0s[512];              // L0 W0e frags, single fp16 (b0|b1)
__device__ ulonglong2 g_B1[1024];       // L1 W1 frags, fp16 hi|lo split
__device__ u64 g_B2s[512];              // L2 W2 frags, single fp16
__device__ ulonglong2 g_BP[2048];       // precompute weight frags (P|Q halves), bf16 hi|lo

// ---------------- packed fp32x2 helpers (final kernel) ----------------
__device__ __forceinline__ u64 pack2(float x) {
    u64 r; asm("mov.b64 %0, {%1, %1};" : "=l"(r) : "f"(x)); return r;
}
__device__ __forceinline__ void ffma2(u64& d, u64 a, u64 b) {
    asm("fma.rn.f32x2 %0, %1, %2, %0;" : "+l"(d) : "l"(a), "l"(b));
}
__device__ __forceinline__ void rank1_16(float xf, const float* w16, u64* a0) {
    u64 xa = pack2(xf);
    const ulonglong2* wr = (const ulonglong2*)w16;
#pragma unroll
    for (int j = 0; j < 4; j++) {
        ulonglong2 w = wr[j];
        ffma2(a0[2 * j],     xa, w.x);
        ffma2(a0[2 * j + 1], xa, w.y);
    }
}

// ---------------- bf16 emulation helpers (pre_kernel path) ----------------
__device__ __forceinline__ u32 bf2pack(float x0, float x1) {
    u32 r;
    asm("cvt.rn.bf16x2.f32 %0, %1, %2;" : "=r"(r) : "f"(x1), "f"(x0));
    return r;
}
__device__ __forceinline__ void split_bf2(float x0, float x1, u32& h, u32& l) {
    h = bf2pack(x0, x1);
    float r0 = x0 - __uint_as_float(h << 16);
    float r1 = x1 - __uint_as_float(h & 0xFFFF0000u);
    l = bf2pack(r0, r1);
}
__device__ __forceinline__ void mma_bf(float c[4], const u32 a[4], u32 b0, u32 b1) {
    asm volatile(
        "mma.sync.aligned.m16n8k16.row.col.f32.bf16.bf16.f32 "
        "{%0,%1,%2,%3}, {%4,%5,%6,%7}, {%8,%9}, {%0,%1,%2,%3};"
        : "+f"(c[0]), "+f"(c[1]), "+f"(c[2]), "+f"(c[3])
        : "r"(a[0]), "r"(a[1]), "r"(a[2]), "r"(a[3]), "r"(b0), "r"(b1));
}
template <int NTC>
__device__ __forceinline__ void gemm_step_bf(float C[][4], const u32 ah[4], const u32 al[4],
                                             const ulonglong2* sB, int kc, int Kc, int lane) {
    u32 bh[NTC][2], bl[NTC][2];
#pragma unroll
    for (int nt = 0; nt < NTC; nt++) {
        ulonglong2 t = sB[(nt * Kc + kc) * 32 + lane];
        bh[nt][0] = (u32)t.x; bl[nt][0] = (u32)(t.x >> 32);
        bh[nt][1] = (u32)t.y; bl[nt][1] = (u32)(t.y >> 32);
    }
#pragma unroll
    for (int nt = 0; nt < NTC; nt++) mma_bf(C[nt], ah, bh[nt][0], bh[nt][1]);
#pragma unroll
    for (int nt = 0; nt < NTC; nt++) mma_bf(C[nt], ah, bl[nt][0], bl[nt][1]);
#pragma unroll
    for (int nt = 0; nt < NTC; nt++) mma_bf(C[nt], al, bh[nt][0], bh[nt][1]);
}

// ---------------- fp16 helpers (edge kernel path) ----------------
__device__ __forceinline__ u32 f16pack(float x0, float x1) {
    u32 r;
    asm("cvt.rn.f16x2.f32 %0, %1, %2;" : "=r"(r) : "f"(x1), "f"(x0));   // low = x0
    return r;
}
__device__ __forceinline__ void mma_f16(float c[4], const u32 a[4], u32 b0, u32 b1) {
    asm volatile(
        "mma.sync.aligned.m16n8k16.row.col.f32.f16.f16.f32 "
        "{%0,%1,%2,%3}, {%4,%5,%6,%7}, {%8,%9}, {%0,%1,%2,%3};"
        : "+f"(c[0]), "+f"(c[1]), "+f"(c[2]), "+f"(c[3])
        : "r"(a[0]), "r"(a[1]), "r"(a[2]), "r"(a[3]), "r"(b0), "r"(b1));
}
// 2-term K-chunk (L1): C += A*Bh + A*Bl
template <int NTC>
__device__ __forceinline__ void gemm_step2(float C[][4], const u32 a[4],
                                           const ulonglong2* sB, int kc, int Kc, int lane) {
    u32 bh[NTC][2], bl[NTC][2];
#pragma unroll
    for (int nt = 0; nt < NTC; nt++) {
        ulonglong2 t = sB[(nt * Kc + kc) * 32 + lane];
        bh[nt][0] = (u32)t.x; bl[nt][0] = (u32)(t.x >> 32);
        bh[nt][1] = (u32)t.y; bl[nt][1] = (u32)(t.y >> 32);
    }
#pragma unroll
    for (int nt = 0; nt < NTC; nt++) mma_f16(C[nt], a, bh[nt][0], bh[nt][1]);
#pragma unroll
    for (int nt = 0; nt < NTC; nt++) mma_f16(C[nt], a, bl[nt][0], bl[nt][1]);
}
// 1-term K-chunk (L0/L2): C += A*B, single fp16 B
template <int NTC>
__device__ __forceinline__ void gemm_step1(float C[][4], const u32 a[4],
                                           const u64* sB, int kc, int Kc, int lane) {
    u64 t[NTC];
#pragma unroll
    for (int nt = 0; nt < NTC; nt++) t[nt] = sB[(nt * Kc + kc) * 32 + lane];
#pragma unroll
    for (int nt = 0; nt < NTC; nt++) mma_f16(C[nt], a, (u32)t[nt], (u32)(t[nt] >> 32));
}
__device__ __forceinline__ void build_a(const float cA[4], const float cB[4], u32 a[4]) {
    a[0] = f16pack(fmaxf(cA[0], 0.f), fmaxf(cA[1], 0.f));
    a[1] = f16pack(fmaxf(cA[2], 0.f), fmaxf(cA[3], 0.f));
    a[2] = f16pack(fmaxf(cB[0], 0.f), fmaxf(cB[1], 0.f));
    a[3] = f16pack(fmaxf(cB[2], 0.f), fmaxf(cB[3], 0.f));
}
__device__ __forceinline__ void red2(float* p, float x, float y) {
    asm volatile("red.global.add.v2.f32 [%0], {%1,%2};" :: "l"(p), "f"(x), "f"(y));
}
// fp16 split: v = h + l, pair-packed
__device__ __forceinline__ void split_f16(float x0, float x1, u32& h, u32& l) {
    __half h0 = __float2half_rn(x0), h1 = __float2half_rn(x1);
    float r0 = x0 - __half2float(h0);
    float r1 = x1 - __half2float(h1);
    __half l0 = __float2half_rn(r0), l1 = __float2half_rn(r1);
    h = ((u32)__half_as_ushort(h1) << 16) | __half_as_ushort(h0);
    l = ((u32)__half_as_ushort(l1) << 16) | __half_as_ushort(l0);
}

// ---------------- setup ----------------
// i<512: B0s (16 frag-slots: nt=f>>1, kc=f&1); [512,1536): B1 split (32 slots);
// [1536,2048): B2s (16 slots); [2048,4096): g_BP bf16 (pre).
__global__ void setup_kernel(const float* __restrict__ w0, const float* __restrict__ w1,
                             const float* __restrict__ w2) {
    int i = blockIdx.x * 256 + threadIdx.x;
    if (i >= 4096) return;
    int lane = i & 31;
    int g = lane >> 2, q = lane & 3;
    if (i < 512) {
        int f = i >> 5;                   // 0..15
        int nt = f >> 1, kc = f & 1;
        int n = nt * 8 + g, k0 = 16 * kc + 2 * q;
        const float* W = w0 + 128 * 64;   // W0e, stride 64
        u32 b0 = f16pack(W[(size_t)k0 * 64 + n],       W[(size_t)(k0 + 1) * 64 + n]);
        u32 b1 = f16pack(W[(size_t)(k0 + 8) * 64 + n], W[(size_t)(k0 + 9) * 64 + n]);
        g_B0s[i] = (u64)b0 | ((u64)b1 << 32);
    } else if (i < 1536) {
        int j = i - 512;
        int f = j >> 5;                   // 0..31
        int nt = f >> 2, kc = f & 3;
        int n = nt * 8 + g, k0 = 16 * kc + 2 * q;
        u32 h0, l0, h1, l1;
        split_f16(w1[(size_t)k0 * 64 + n],       w1[(size_t)(k0 + 1) * 64 + n], h0, l0);
        split_f16(w1[(size_t)(k0 + 8) * 64 + n], w1[(size_t)(k0 + 9) * 64 + n], h1, l1);
        ulonglong2 t;
        t.x = (u64)h0 | ((u64)l0 << 32);
        t.y = (u64)h1 | ((u64)l1 << 32);
        g_B1[j] = t;
    } else if (i < 2048) {
        int j = i - 1536;
        int f = j >> 5;                   // 0..15
        int nt = f >> 2, kc = f & 3;
        int n = nt * 8 + g, k0 = 16 * kc + 2 * q;
        u32 b0 = f16pack(w2[(size_t)k0 * 32 + n],       w2[(size_t)(k0 + 1) * 32 + n]);
        u32 b1 = f16pack(w2[(size_t)(k0 + 8) * 32 + n], w2[(size_t)(k0 + 9) * 32 + n]);
        g_B2s[j] = (u64)b0 | ((u64)b1 << 32);
    } else {
        int ff = (i - 2048) >> 5;
        int nt = ff >> 2, kc = ff & 3;
        int isq = (nt >= 8) ? 32 : 0;
        int nidx = (nt & 7) * 8 + g;
        int k0 = 16 * kc + 2 * q;
        int r00 = ((k0     < 32) ? k0     : k0 + 32) + isq;
        int r01 = ((k0 + 1 < 32) ? k0 + 1 : k0 + 33) + isq;
        int r10 = ((k0 + 8 < 32) ? k0 + 8 : k0 + 40) + isq;
        int r11 = ((k0 + 9 < 32) ? k0 + 9 : k0 + 41) + isq;
        u32 h0, l0, h1, l1;
        split_bf2(w0[(size_t)r00 * 64 + nidx], w0[(size_t)r01 * 64 + nidx], h0, l0);
        split_bf2(w0[(size_t)r10 * 64 + nidx], w0[(size_t)r11 * 64 + nidx], h1, l1);
        ulonglong2 t;
        t.x = (u64)h0 | ((u64)l0 << 32);
        t.y = (u64)h1 | ((u64)l1 << 32);
        g_BP[i - 2048] = t;
    }
}

// ---------------- precompute: P|Q = [h_s|h_d] @ W' via bf16-3term MMA; zeros g_agg ----------------
__global__ void __launch_bounds__(256, 1)
pre_kernel(const float* __restrict__ h_s, const float* __restrict__ h_d,
           const float* __restrict__ b0) {
    extern __shared__ ulonglong2 smem_v2[];
    float* s_b0 = (float*)(smem_v2 + 2048);
    const int tid = threadIdx.x, wid = tid >> 5, lane = tid & 31;
    const int g = lane >> 2, q = lane & 3;
    for (int i = tid; i < 2048; i += 256) smem_v2[i] = g_BP[i];
    if (tid < 64) s_b0[tid] = b0[tid];
    __syncthreads();

    int n0 = (blockIdx.x * 8 + wid) * 16;
    if (n0 >= NN) return;

    float C[16][4];
#pragma unroll
    for (int nt = 0; nt < 8; nt++) {
        C[nt][0] = 0.f; C[nt][1] = 0.f; C[nt][2] = 0.f; C[nt][3] = 0.f;
        float b0v = s_b0[nt * 8 + 2 * q], b1v = s_b0[nt * 8 + 2 * q + 1];
        C[8 + nt][0] = b0v; C[8 + nt][1] = b1v; C[8 + nt][2] = b0v; C[8 + nt][3] = b1v;
    }
#pragma unroll
    for (int kc = 0; kc < 4; kc++) {
        const float* src = (kc < 2) ? h_s : h_d;
        int off = (kc & 1) * 16 + 2 * q;
        float2 x0 = *(const float2*)(src + (size_t)(n0 + g) * 32 + off);
        float2 x1 = *(const float2*)(src + (size_t)(n0 + 8 + g) * 32 + off);
        float2 x2 = *(const float2*)(src + (size_t)(n0 + g) * 32 + off + 8);
        float2 x3 = *(const float2*)(src + (size_t)(n0 + 8 + g) * 32 + off + 8);
        u32 ah[4], al[4];
        split_bf2(x0.x, x0.y, ah[0], al[0]);
        split_bf2(x1.x, x1.y, ah[1], al[1]);
        split_bf2(x2.x, x2.y, ah[2], al[2]);
        split_bf2(x3.x, x3.y, ah[3], al[3]);
        gemm_step_bf<8>(C,     ah, al, smem_v2,           kc, 4, lane);   // P
        gemm_step_bf<8>(C + 8, ah, al, smem_v2 + 32 * 32, kc, 4, lane);   // Q
    }
    // store fragment-major: [n][q*16 + nt*2]
#pragma unroll
    for (int j = 0; j < 4; j++) {
        *(float4*)(g_P + (size_t)(n0 + g)     * 64 + q * 16 + 4 * j) =
            make_float4(C[2*j][0], C[2*j][1], C[2*j+1][0], C[2*j+1][1]);
        *(float4*)(g_P + (size_t)(n0 + 8 + g) * 64 + q * 16 + 4 * j) =
            make_float4(C[2*j][2], C[2*j][3], C[2*j+1][2], C[2*j+1][3]);
        *(float4*)(g_Q + (size_t)(n0 + g)     * 64 + q * 16 + 4 * j) =
            make_float4(C[8+2*j][0], C[8+2*j][1], C[8+2*j+1][0], C[8+2*j+1][1]);
        *(float4*)(g_Q + (size_t)(n0 + 8 + g) * 64 + q * 16 + 4 * j) =
            make_float4(C[8+2*j][2], C[8+2*j][3], C[8+2*j+1][2], C[8+2*j+1][3]);
    }
    float4 z = make_float4(0.f, 0.f, 0.f, 0.f);
    float4* ag = (float4*)(g_agg + (size_t)n0 * 32);
#pragma unroll
    for (int i = 0; i < 4; i++) ag[lane + 32 * i] = z;
}

// ---------------- edge kernel: fp16 MMA MLP (L0/L2 1-term, L1 2-term) ----------------
// smem: sB0s u64[512] @0 (4KB), sB1 u2[1024] @4096 (16KB), sB2s u64[512] @20480 (4KB),
//       biases @24576
#define SMEM_BYTES (24576 + 96 * 4)

__global__ void __launch_bounds__(ET, 1)
edge_kernel(const float* __restrict__ h_d, const float* __restrict__ ef,
            const int* __restrict__ si, const int* __restrict__ ri,
            const float* __restrict__ b1, const float* __restrict__ b2) {
    extern __shared__ char smem_c[];
    u64* sB0s = (u64*)smem_c;
    ulonglong2* sB1 = (ulonglong2*)(smem_c + 4096);
    u64* sB2s = (u64*)(smem_c + 20480);
    float* s_b1 = (float*)(smem_c + 24576);
    float* s_b2 = s_b1 + 64;

    const int tid = threadIdx.x, wid = tid >> 5, lane = tid & 31;
    for (int i = tid; i < 512; i += ET) sB0s[i] = g_B0s[i];
    for (int i = tid; i < 1024; i += ET) sB1[i] = g_B1[i];
    for (int i = tid; i < 512; i += ET) sB2s[i] = g_B2s[i];
    if (tid < 64) s_b1[tid] = b1[tid];
    if (tid < 32) s_b2[tid] = b2[tid];
    __syncthreads();

    const int g = lane >> 2, q = lane & 3;
    const int col2 = 2 * q;
    const int WPC = ET / 32;

#pragma unroll 1
    for (int base = blockIdx.x * (WPC * 16) + wid * 16; base < NE; base += NBLK * (WPC * 16)) {
        int e0 = base + g, e1 = base + 8 + g;
        bool v0 = e0 < NE, v1 = e1 < NE;
        int e0c = v0 ? e0 : NE - 1;
        int e1c = v1 ? e1 : NE - 1;
        int s0 = si[e0c], rc0 = ri[e0c];
        int s1 = si[e1c], rc1 = ri[e1c];

        // ===== layer 0: C init from P[s]+Q[r] (exact fp32) =====
        float C[8][4];
        {
            const float4* P0 = (const float4*)(g_P + (size_t)s0  * 64 + q * 16);
            const float4* Q0 = (const float4*)(g_Q + (size_t)rc0 * 64 + q * 16);
            const float4* P1 = (const float4*)(g_P + (size_t)s1  * 64 + q * 16);
            const float4* Q1 = (const float4*)(g_Q + (size_t)rc1 * 64 + q * 16);
#pragma unroll
            for (int j = 0; j < 4; j++) {
                float4 p = P0[j], qq = Q0[j];
                C[2*j][0]   = p.x + qq.x; C[2*j][1]   = p.y + qq.y;
                C[2*j+1][0] = p.z + qq.z; C[2*j+1][1] = p.w + qq.w;
                p = P1[j]; qq = Q1[j];
                C[2*j][2]   = p.x + qq.x; C[2*j][3]   = p.y + qq.y;
                C[2*j+1][2] = p.z + qq.z; C[2*j+1][3] = p.w + qq.w;
            }
        }
        // ===== layer 0: += ef @ W0e (1-term) =====
#pragma unroll
        for (int kc = 0; kc < 2; kc++) {
            int off = 16 * kc + col2;
            float2 x0 = *(const float2*)(ef + (size_t)e0c * 32 + off);
            float2 x1 = *(const float2*)(ef + (size_t)e1c * 32 + off);
            float2 x2 = *(const float2*)(ef + (size_t)e0c * 32 + off + 8);
            float2 x3 = *(const float2*)(ef + (size_t)e1c * 32 + off + 8);
            u32 a[4];
            a[0] = f16pack(x0.x, x0.y);
            a[1] = f16pack(x1.x, x1.y);
            a[2] = f16pack(x2.x, x2.y);
            a[3] = f16pack(x3.x, x3.y);
            gemm_step1<8>(C, a, sB0s, kc, 2, lane);
        }

        // ===== layer 1 (2-term) =====
        float C1[8][4];
#pragma unroll
        for (int nt = 0; nt < 8; nt++) {
            float bb0 = s_b1[nt * 8 + col2], bb1 = s_b1[nt * 8 + col2 + 1];
            C1[nt][0] = bb0; C1[nt][1] = bb1; C1[nt][2] = bb0; C1[nt][3] = bb1;
        }
#pragma unroll
        for (int kc = 0; kc < 4; kc++) {
            u32 a[4];
            build_a(C[2 * kc], C[2 * kc + 1], a);
            gemm_step2<8>(C1, a, sB1, kc, 4, lane);
        }

        // ===== layer 2 (1-term) =====
        float C2[4][4];
#pragma unroll
        for (int nt = 0; nt < 4; nt++) {
            float bb0 = s_b2[nt * 8 + col2], bb1 = s_b2[nt * 8 + col2 + 1];
            C2[nt][0] = bb0; C2[nt][1] = bb1; C2[nt][2] = bb0; C2[nt][3] = bb1;
        }
#pragma unroll
        for (int kc = 0; kc < 4; kc++) {
            u32 a[4];
            build_a(C1[2 * kc], C1[2 * kc + 1], a);
            gemm_step1<4>(C2, a, sB2s, kc, 4, lane);
        }

        // ===== epilogue: relu(psi) * (h_dj - h_di), vector scatter-add =====
#pragma unroll
        for (int nt = 0; nt < 4; nt++) {
            int cc = nt * 8 + col2;
            if (v0) {
                float2 dj = *(const float2*)(h_d + (size_t)rc0 * 32 + cc);
                float2 di = *(const float2*)(h_d + (size_t)s0 * 32 + cc);
                red2(g_agg + (size_t)rc0 * 32 + cc,
                     fmaxf(C2[nt][0], 0.f) * (dj.x - di.x),
                     fmaxf(C2[nt][1], 0.f) * (dj.y - di.y));
            }
            if (v1) {
                float2 dj = *(const float2*)(h_d + (size_t)rc1 * 32 + cc);
                float2 di = *(const float2*)(h_d + (size_t)s1 * 32 + cc);
                red2(g_agg + (size_t)rc1 * 32 + cc,
                     fmaxf(C2[nt][2], 0.f) * (dj.x - di.x),
                     fmaxf(C2[nt][3], 0.f) * (dj.y - di.y));
            }
        }
    }
}

// out[n] = h_d_prev[n] + agg[n] @ W   (2 threads per node, 16 outputs each)
__global__ void __launch_bounds__(256)
final_kernel(const float* __restrict__ h_d, const float* __restrict__ W,
             float* __restrict__ out) {
    __shared__ float sW[1024];
    int tid = threadIdx.x;
    {
        float4* d4 = (float4*)sW;
        const float4* s4 = (const float4*)W;
        for (int i = tid; i < 256; i += 256) d4[i] = s4[i];
    }
    __syncthreads();
    int idx = blockIdx.x * 256 + tid;
    int n = idx >> 1, half = idx & 1;
    if (n >= NN) return;

    u64 acc[8];
    {
        const ulonglong2* hp = (const ulonglong2*)(h_d + (size_t)n * 32 + half * 16);
#pragma unroll
        for (int j = 0; j < 4; j++) {
            ulonglong2 t = hp[j];
            acc[2 * j] = t.x; acc[2 * j + 1] = t.y;
        }
    }
    const float4* ap = (const float4*)(g_agg + (size_t)n * 32);
    const float* wb = sW + half * 16;
#pragma unroll
    for (int i = 0; i < 8; i++) {
        float4 a = ap[i];
        rank1_16(a.x, wb + (4 * i) * 32,     acc);
        rank1_16(a.y, wb + (4 * i + 1) * 32, acc);
        rank1_16(a.z, wb + (4 * i + 2) * 32, acc);
        rank1_16(a.w, wb + (4 * i + 3) * 32, acc);
    }
    ulonglong2* op = (ulonglong2*)(out + (size_t)n * 32 + half * 16);
#pragma unroll
    for (int j = 0; j < 4; j++) {
        ulonglong2 t; t.x = acc[2 * j]; t.y = acc[2 * j + 1];
        op[j] = t;
    }
}

extern "C" void kernel_launch(void* const* d_in, const int* in_sizes, int n_in,
                              void* d_out, int out_size) {
    const float* h_d = (const float*)d_in[0];
    const float* h_s = (const float*)d_in[1];
    const float* ef  = (const float*)d_in[2];
    const int*   si  = (const int*)d_in[3];
    const int*   ri  = (const int*)d_in[4];
    const float* w0  = (const float*)d_in[5];
    const float* b0  = (const float*)d_in[6];
    const float* w1  = (const float*)d_in[7];
    const float* b1  = (const float*)d_in[8];
    const float* w2  = (const float*)d_in[9];
    const float* b2  = (const float*)d_in[10];
    const float* W   = (const float*)d_in[11];
    float* out = (float*)d_out;

    cudaFuncSetAttribute(edge_kernel, cudaFuncAttributeMaxDynamicSharedMemorySize,
                         SMEM_BYTES);
    cudaFuncSetAttribute(pre_kernel, cudaFuncAttributeMaxDynamicSharedMemorySize,
                         2048 * 16 + 64 * 4);

    setup_kernel<<<16, 256>>>(w0, w1, w2);
    pre_kernel<<<782, 256, 2048 * 16 + 64 * 4>>>(h_s, h_d, b0);
    edge_kernel<<<NBLK, ET, SMEM_BYTES>>>(h_d, ef, si, ri, b1, b2);
    final_kernel<<<(2 * NN + 255) / 256, 256>>>(h_d, W, out);
}

// round 14
// speedup vs baseline: 3.0123x; 1.0711x over previous
#include <cuda_runtime.h>
#include <cuda_fp16.h>
#include <cstdint>

#define NN 100000
#define NE 800000
#define NBLK 148
#define ET 512          // edge kernel threads (16 warps)

typedef unsigned long long u64;
typedef unsigned int u32;

// scratch (allocation-free rule: __device__ globals)
__device__ float g_agg[NN * 32];
__device__ float g_P[NN * 64];          // fragment-major: [n][q*16 + nt*2 + c]
__device__ float g_Q[NN * 64];
__device__ u64 g_B0s[512];              // L0 W0e frags, single fp16 (b0|b1)
__device__ u64 g_B1s[1024];             // L1 W1 frags, single fp16
__device__ u64 g_B2s[512];              // L2 W2 frags, single fp16
__device__ ulonglong2 g_BP[2048];       // precompute weight frags (P|Q halves), bf16 hi|lo

// ---------------- packed fp32x2 helpers (final kernel) ----------------
__device__ __forceinline__ u64 pack2(float x) {
    u64 r; asm("mov.b64 %0, {%1, %1};" : "=l"(r) : "f"(x)); return r;
}
__device__ __forceinline__ void ffma2(u64& d, u64 a, u64 b) {
    asm("fma.rn.f32x2 %0, %1, %2, %0;" : "+l"(d) : "l"(a), "l"(b));
}
__device__ __forceinline__ void rank1_16(float xf, const float* w16, u64* a0) {
    u64 xa = pack2(xf);
    const ulonglong2* wr = (const ulonglong2*)w16;
#pragma unroll
    for (int j = 0; j < 4; j++) {
        ulonglong2 w = wr[j];
        ffma2(a0[2 * j],     xa, w.x);
        ffma2(a0[2 * j + 1], xa, w.y);
    }
}

// ---------------- bf16 emulation helpers (pre_kernel path) ----------------
__device__ __forceinline__ u32 bf2pack(float x0, float x1) {
    u32 r;
    asm("cvt.rn.bf16x2.f32 %0, %1, %2;" : "=r"(r) : "f"(x1), "f"(x0));
    return r;
}
__device__ __forceinline__ void split_bf2(float x0, float x1, u32& h, u32& l) {
    h = bf2pack(x0, x1);
    float r0 = x0 - __uint_as_float(h << 16);
    float r1 = x1 - __uint_as_float(h & 0xFFFF0000u);
    l = bf2pack(r0, r1);
}
__device__ __forceinline__ void mma_bf(float c[4], const u32 a[4], u32 b0, u32 b1) {
    asm volatile(
        "mma.sync.aligned.m16n8k16.row.col.f32.bf16.bf16.f32 "
        "{%0,%1,%2,%3}, {%4,%5,%6,%7}, {%8,%9}, {%0,%1,%2,%3};"
        : "+f"(c[0]), "+f"(c[1]), "+f"(c[2]), "+f"(c[3])
        : "r"(a[0]), "r"(a[1]), "r"(a[2]), "r"(a[3]), "r"(b0), "r"(b1));
}
template <int NTC>
__device__ __forceinline__ void gemm_step_bf(float C[][4], const u32 ah[4], const u32 al[4],
                                             const ulonglong2* sB, int kc, int Kc, int lane) {
    u32 bh[NTC][2], bl[NTC][2];
#pragma unroll
    for (int nt = 0; nt < NTC; nt++) {
        ulonglong2 t = sB[(nt * Kc + kc) * 32 + lane];
        bh[nt][0] = (u32)t.x; bl[nt][0] = (u32)(t.x >> 32);
        bh[nt][1] = (u32)t.y; bl[nt][1] = (u32)(t.y >> 32);
    }
#pragma unroll
    for (int nt = 0; nt < NTC; nt++) mma_bf(C[nt], ah, bh[nt][0], bh[nt][1]);
#pragma unroll
    for (int nt = 0; nt < NTC; nt++) mma_bf(C[nt], ah, bl[nt][0], bl[nt][1]);
#pragma unroll
    for (int nt = 0; nt < NTC; nt++) mma_bf(C[nt], al, bh[nt][0], bh[nt][1]);
}

// ---------------- fp16 helpers (edge kernel path) ----------------
__device__ __forceinline__ u32 f16pack(float x0, float x1) {
    u32 r;
    asm("cvt.rn.f16x2.f32 %0, %1, %2;" : "=r"(r) : "f"(x1), "f"(x0));   // low = x0
    return r;
}
__device__ __forceinline__ void mma_f16(float c[4], const u32 a[4], u32 b0, u32 b1) {
    asm volatile(
        "mma.sync.aligned.m16n8k16.row.col.f32.f16.f16.f32 "
        "{%0,%1,%2,%3}, {%4,%5,%6,%7}, {%8,%9}, {%0,%1,%2,%3};"
        : "+f"(c[0]), "+f"(c[1]), "+f"(c[2]), "+f"(c[3])
        : "r"(a[0]), "r"(a[1]), "r"(a[2]), "r"(a[3]), "r"(b0), "r"(b1));
}
// 1-term K-chunk: C += A*B, single fp16 B
template <int NTC>
__device__ __forceinline__ void gemm_step1(float C[][4], const u32 a[4],
                                           const u64* sB, int kc, int Kc, int lane) {
    u64 t[NTC];
#pragma unroll
    for (int nt = 0; nt < NTC; nt++) t[nt] = sB[(nt * Kc + kc) * 32 + lane];
#pragma unroll
    for (int nt = 0; nt < NTC; nt++) mma_f16(C[nt], a, (u32)t[nt], (u32)(t[nt] >> 32));
}
__device__ __forceinline__ void build_a(const float cA[4], const float cB[4], u32 a[4]) {
    a[0] = f16pack(fmaxf(cA[0], 0.f), fmaxf(cA[1], 0.f));
    a[1] = f16pack(fmaxf(cA[2], 0.f), fmaxf(cA[3], 0.f));
    a[2] = f16pack(fmaxf(cB[0], 0.f), fmaxf(cB[1], 0.f));
    a[3] = f16pack(fmaxf(cB[2], 0.f), fmaxf(cB[3], 0.f));
}
__device__ __forceinline__ void red2(float* p, float x, float y) {
    asm volatile("red.global.add.v2.f32 [%0], {%1,%2};" :: "l"(p), "f"(x), "f"(y));
}

// ---------------- setup ----------------
// i<512: B0s; [512,1536): B1s; [1536,2048): B2s; [2048,4096): g_BP bf16 (pre).
__global__ void setup_kernel(const float* __restrict__ w0, const float* __restrict__ w1,
                             const float* __restrict__ w2) {
    int i = blockIdx.x * 256 + threadIdx.x;
    if (i >= 4096) return;
    int lane = i & 31;
    int g = lane >> 2, q = lane & 3;
    if (i < 512) {
        int f = i >> 5;                   // 0..15: nt = f>>1, kc = f&1
        int nt = f >> 1, kc = f & 1;
        int n = nt * 8 + g, k0 = 16 * kc + 2 * q;
        const float* W = w0 + 128 * 64;   // W0e, stride 64
        u32 b0 = f16pack(W[(size_t)k0 * 64 + n],       W[(size_t)(k0 + 1) * 64 + n]);
        u32 b1 = f16pack(W[(size_t)(k0 + 8) * 64 + n], W[(size_t)(k0 + 9) * 64 + n]);
        g_B0s[i] = (u64)b0 | ((u64)b1 << 32);
    } else if (i < 1536) {
        int j = i - 512;
        int f = j >> 5;                   // 0..31: nt = f>>2, kc = f&3
        int nt = f >> 2, kc = f & 3;
        int n = nt * 8 + g, k0 = 16 * kc + 2 * q;
        u32 b0 = f16pack(w1[(size_t)k0 * 64 + n],       w1[(size_t)(k0 + 1) * 64 + n]);
        u32 b1 = f16pack(w1[(size_t)(k0 + 8) * 64 + n], w1[(size_t)(k0 + 9) * 64 + n]);
        g_B1s[j] = (u64)b0 | ((u64)b1 << 32);
    } else if (i < 2048) {
        int j = i - 1536;
        int f = j >> 5;                   // 0..15: nt = f>>2, kc = f&3
        int nt = f >> 2, kc = f & 3;
        int n = nt * 8 + g, k0 = 16 * kc + 2 * q;
        u32 b0 = f16pack(w2[(size_t)k0 * 32 + n],       w2[(size_t)(k0 + 1) * 32 + n]);
        u32 b1 = f16pack(w2[(size_t)(k0 + 8) * 32 + n], w2[(size_t)(k0 + 9) * 32 + n]);
        g_B2s[j] = (u64)b0 | ((u64)b1 << 32);
    } else {
        int ff = (i - 2048) >> 5;
        int nt = ff >> 2, kc = ff & 3;
        int isq = (nt >= 8) ? 32 : 0;
        int nidx = (nt & 7) * 8 + g;
        int k0 = 16 * kc + 2 * q;
        int r00 = ((k0     < 32) ? k0     : k0 + 32) + isq;
        int r01 = ((k0 + 1 < 32) ? k0 + 1 : k0 + 33) + isq;
        int r10 = ((k0 + 8 < 32) ? k0 + 8 : k0 + 40) + isq;
        int r11 = ((k0 + 9 < 32) ? k0 + 9 : k0 + 41) + isq;
        u32 h0, l0, h1, l1;
        split_bf2(w0[(size_t)r00 * 64 + nidx], w0[(size_t)r01 * 64 + nidx], h0, l0);
        split_bf2(w0[(size_t)r10 * 64 + nidx], w0[(size_t)r11 * 64 + nidx], h1, l1);
        ulonglong2 t;
        t.x = (u64)h0 | ((u64)l0 << 32);
        t.y = (u64)h1 | ((u64)l1 << 32);
        g_BP[i - 2048] = t;
    }
}

// ---------------- precompute: P|Q = [h_s|h_d] @ W' via bf16-3term MMA; zeros g_agg ----------------
__global__ void __launch_bounds__(256, 1)
pre_kernel(const float* __restrict__ h_s, const float* __restrict__ h_d,
           const float* __restrict__ b0) {
    extern __shared__ ulonglong2 smem_v2[];
    float* s_b0 = (float*)(smem_v2 + 2048);
    const int tid = threadIdx.x, wid = tid >> 5, lane = tid & 31;
    const int g = lane >> 2, q = lane & 3;
    for (int i = tid; i < 2048; i += 256) smem_v2[i] = g_BP[i];
    if (tid < 64) s_b0[tid] = b0[tid];
    __syncthreads();

    int n0 = (blockIdx.x * 8 + wid) * 16;
    if (n0 >= NN) return;

    float C[16][4];
#pragma unroll
    for (int nt = 0; nt < 8; nt++) {
        C[nt][0] = 0.f; C[nt][1] = 0.f; C[nt][2] = 0.f; C[nt][3] = 0.f;
        float b0v = s_b0[nt * 8 + 2 * q], b1v = s_b0[nt * 8 + 2 * q + 1];
        C[8 + nt][0] = b0v; C[8 + nt][1] = b1v; C[8 + nt][2] = b0v; C[8 + nt][3] = b1v;
    }
#pragma unroll
    for (int kc = 0; kc < 4; kc++) {
        const float* src = (kc < 2) ? h_s : h_d;
        int off = (kc & 1) * 16 + 2 * q;
        float2 x0 = *(const float2*)(src + (size_t)(n0 + g) * 32 + off);
        float2 x1 = *(const float2*)(src + (size_t)(n0 + 8 + g) * 32 + off);
        float2 x2 = *(const float2*)(src + (size_t)(n0 + g) * 32 + off + 8);
        float2 x3 = *(const float2*)(src + (size_t)(n0 + 8 + g) * 32 + off + 8);
        u32 ah[4], al[4];
        split_bf2(x0.x, x0.y, ah[0], al[0]);
        split_bf2(x1.x, x1.y, ah[1], al[1]);
        split_bf2(x2.x, x2.y, ah[2], al[2]);
        split_bf2(x3.x, x3.y, ah[3], al[3]);
        gemm_step_bf<8>(C,     ah, al, smem_v2,           kc, 4, lane);   // P
        gemm_step_bf<8>(C + 8, ah, al, smem_v2 + 32 * 32, kc, 4, lane);   // Q
    }
    // store fragment-major: [n][q*16 + nt*2]
#pragma unroll
    for (int j = 0; j < 4; j++) {
        *(float4*)(g_P + (size_t)(n0 + g)     * 64 + q * 16 + 4 * j) =
            make_float4(C[2*j][0], C[2*j][1], C[2*j+1][0], C[2*j+1][1]);
        *(float4*)(g_P + (size_t)(n0 + 8 + g) * 64 + q * 16 + 4 * j) =
            make_float4(C[2*j][2], C[2*j][3], C[2*j+1][2], C[2*j+1][3]);
        *(float4*)(g_Q + (size_t)(n0 + g)     * 64 + q * 16 + 4 * j) =
            make_float4(C[8+2*j][0], C[8+2*j][1], C[8+2*j+1][0], C[8+2*j+1][1]);
        *(float4*)(g_Q + (size_t)(n0 + 8 + g) * 64 + q * 16 + 4 * j) =
            make_float4(C[8+2*j][2], C[8+2*j][3], C[8+2*j+1][2], C[8+2*j+1][3]);
    }
    float4 z = make_float4(0.f, 0.f, 0.f, 0.f);
    float4* ag = (float4*)(g_agg + (size_t)n0 * 32);
#pragma unroll
    for (int i = 0; i < 4; i++) ag[lane + 32 * i] = z;
}

// ---------------- edge kernel: fp16 1-term MMA MLP (all layers) ----------------
// smem: sB0s u64[512] @0 (4KB), sB1s u64[1024] @4096 (8KB), sB2s u64[512] @12288 (4KB),
//       biases @16384
#define SMEM_BYTES (16384 + 96 * 4)

__global__ void __launch_bounds__(ET, 1)
edge_kernel(const float* __restrict__ h_d, const float* __restrict__ ef,
            const int* __restrict__ si, const int* __restrict__ ri,
            const float* __restrict__ b1, const float* __restrict__ b2) {
    extern __shared__ char smem_c[];
    u64* sB0s = (u64*)smem_c;
    u64* sB1s = (u64*)(smem_c + 4096);
    u64* sB2s = (u64*)(smem_c + 12288);
    float* s_b1 = (float*)(smem_c + 16384);
    float* s_b2 = s_b1 + 64;

    const int tid = threadIdx.x, wid = tid >> 5, lane = tid & 31;
    for (int i = tid; i < 512; i += ET) sB0s[i] = g_B0s[i];
    for (int i = tid; i < 1024; i += ET) sB1s[i] = g_B1s[i];
    for (int i = tid; i < 512; i += ET) sB2s[i] = g_B2s[i];
    if (tid < 64) s_b1[tid] = b1[tid];
    if (tid < 32) s_b2[tid] = b2[tid];
    __syncthreads();

    const int g = lane >> 2, q = lane & 3;
    const int col2 = 2 * q;
    const int WPC = ET / 32;

#pragma unroll 1
    for (int base = blockIdx.x * (WPC * 16) + wid * 16; base < NE; base += NBLK * (WPC * 16)) {
        int e0 = base + g, e1 = base + 8 + g;
        bool v0 = e0 < NE, v1 = e1 < NE;
        int e0c = v0 ? e0 : NE - 1;
        int e1c = v1 ? e1 : NE - 1;
        int s0 = si[e0c], rc0 = ri[e0c];
        int s1 = si[e1c], rc1 = ri[e1c];

        // ===== layer 0: C init from P[s]+Q[r] (exact fp32) =====
        float C[8][4];
        {
            const float4* P0 = (const float4*)(g_P + (size_t)s0  * 64 + q * 16);
            const float4* Q0 = (const float4*)(g_Q + (size_t)rc0 * 64 + q * 16);
            const float4* P1 = (const float4*)(g_P + (size_t)s1  * 64 + q * 16);
            const float4* Q1 = (const float4*)(g_Q + (size_t)rc1 * 64 + q * 16);
#pragma unroll
            for (int j = 0; j < 4; j++) {
                float4 p = P0[j], qq = Q0[j];
                C[2*j][0]   = p.x + qq.x; C[2*j][1]   = p.y + qq.y;
                C[2*j+1][0] = p.z + qq.z; C[2*j+1][1] = p.w + qq.w;
                p = P1[j]; qq = Q1[j];
                C[2*j][2]   = p.x + qq.x; C[2*j][3]   = p.y + qq.y;
                C[2*j+1][2] = p.z + qq.z; C[2*j+1][3] = p.w + qq.w;
            }
        }
        // ===== layer 0: += ef @ W0e (1-term) =====
#pragma unroll
        for (int kc = 0; kc < 2; kc++) {
            int off = 16 * kc + col2;
            float2 x0 = *(const float2*)(ef + (size_t)e0c * 32 + off);
            float2 x1 = *(const float2*)(ef + (size_t)e1c * 32 + off);
            float2 x2 = *(const float2*)(ef + (size_t)e0c * 32 + off + 8);
            float2 x3 = *(const float2*)(ef + (size_t)e1c * 32 + off + 8);
            u32 a[4];
            a[0] = f16pack(x0.x, x0.y);
            a[1] = f16pack(x1.x, x1.y);
            a[2] = f16pack(x2.x, x2.y);
            a[3] = f16pack(x3.x, x3.y);
            gemm_step1<8>(C, a, sB0s, kc, 2, lane);
        }

        // ===== layer 1 (1-term) =====
        float C1[8][4];
#pragma unroll
        for (int nt = 0; nt < 8; nt++) {
            float bb0 = s_b1[nt * 8 + col2], bb1 = s_b1[nt * 8 + col2 + 1];
            C1[nt][0] = bb0; C1[nt][1] = bb1; C1[nt][2] = bb0; C1[nt][3] = bb1;
        }
#pragma unroll
        for (int kc = 0; kc < 4; kc++) {
            u32 a[4];
            build_a(C[2 * kc], C[2 * kc + 1], a);
            gemm_step1<8>(C1, a, sB1s, kc, 4, lane);
        }

        // ===== layer 2 (1-term) =====
        float C2[4][4];
#pragma unroll
        for (int nt = 0; nt < 4; nt++) {
            float bb0 = s_b2[nt * 8 + col2], bb1 = s_b2[nt * 8 + col2 + 1];
            C2[nt][0] = bb0; C2[nt][1] = bb1; C2[nt][2] = bb0; C2[nt][3] = bb1;
        }
#pragma unroll
        for (int kc = 0; kc < 4; kc++) {
            u32 a[4];
            build_a(C1[2 * kc], C1[2 * kc + 1], a);
            gemm_step1<4>(C2, a, sB2s, kc, 4, lane);
        }

        // ===== epilogue: relu(psi) * (h_dj - h_di), vector scatter-add =====
#pragma unroll
        for (int nt = 0; nt < 4; nt++) {
            int cc = nt * 8 + col2;
            if (v0) {
                float2 dj = *(const float2*)(h_d + (size_t)rc0 * 32 + cc);
                float2 di = *(const float2*)(h_d + (size_t)s0 * 32 + cc);
                red2(g_agg + (size_t)rc0 * 32 + cc,
                     fmaxf(C2[nt][0], 0.f) * (dj.x - di.x),
                     fmaxf(C2[nt][1], 0.f) * (dj.y - di.y));
            }
            if (v1) {
                float2 dj = *(const float2*)(h_d + (size_t)rc1 * 32 + cc);
                float2 di = *(const float2*)(h_d + (size_t)s1 * 32 + cc);
                red2(g_agg + (size_t)rc1 * 32 + cc,
                     fmaxf(C2[nt][2], 0.f) * (dj.x - di.x),
                     fmaxf(C2[nt][3], 0.f) * (dj.y - di.y));
            }
        }
    }
}

// out[n] = h_d_prev[n] + agg[n] @ W   (2 threads per node, 16 outputs each)
__global__ void __launch_bounds__(256)
final_kernel(const float* __restrict__ h_d, const float* __restrict__ W,
             float* __restrict__ out) {
    __shared__ float sW[1024];
    int tid = threadIdx.x;
    {
        float4* d4 = (float4*)sW;
        const float4* s4 = (const float4*)W;
        for (int i = tid; i < 256; i += 256) d4[i] = s4[i];
    }
    __syncthreads();
    int idx = blockIdx.x * 256 + tid;
    int n = idx >> 1, half = idx & 1;
    if (n >= NN) return;

    u64 acc[8];
    {
        const ulonglong2* hp = (const ulonglong2*)(h_d + (size_t)n * 32 + half * 16);
#pragma unroll
        for (int j = 0; j < 4; j++) {
            ulonglong2 t = hp[j];
            acc[2 * j] = t.x; acc[2 * j + 1] = t.y;
        }
    }
    const float4* ap = (const float4*)(g_agg + (size_t)n * 32);
    const float* wb = sW + half * 16;
#pragma unroll
    for (int i = 0; i < 8; i++) {
        float4 a = ap[i];
        rank1_16(a.x, wb + (4 * i) * 32,     acc);
        rank1_16(a.y, wb + (4 * i + 1) * 32, acc);
        rank1_16(a.z, wb + (4 * i + 2) * 32, acc);
        rank1_16(a.w, wb + (4 * i + 3) * 32, acc);
    }
    ulonglong2* op = (ulonglong2*)(out + (size_t)n * 32 + half * 16);
#pragma unroll
    for (int j = 0; j < 4; j++) {
        ulonglong2 t; t.x = acc[2 * j]; t.y = acc[2 * j + 1];
        op[j] = t;
    }
}

extern "C" void kernel_launch(void* const* d_in, const int* in_sizes, int n_in,
                              void* d_out, int out_size) {
    const float* h_d = (const float*)d_in[0];
    const float* h_s = (const float*)d_in[1];
    const float* ef  = (const float*)d_in[2];
    const int*   si  = (const int*)d_in[3];
    const int*   ri  = (const int*)d_in[4];
    const float* w0  = (const float*)d_in[5];
    const float* b0  = (const float*)d_in[6];
    const float* w1  = (const float*)d_in[7];
    const float* b1  = (const float*)d_in[8];
    const float* w2  = (const float*)d_in[9];
    const float* b2  = (const float*)d_in[10];
    const float* W   = (const float*)d_in[11];
    float* out = (float*)d_out;

    cudaFuncSetAttribute(edge_kernel, cudaFuncAttributeMaxDynamicSharedMemorySize,
                         SMEM_BYTES);
    cudaFuncSetAttribute(pre_kernel, cudaFuncAttributeMaxDynamicSharedMemorySize,
                         2048 * 16 + 64 * 4);

    setup_kernel<<<16, 256>>>(w0, w1, w2);
    pre_kernel<<<782, 256, 2048 * 16 + 64 * 4>>>(h_s, h_d, b0);
    edge_kernel<<<NBLK, ET, SMEM_BYTES>>>(h_d, ef, si, ri, b1, b2);
    final_kernel<<<(2 * NN + 255) / 256, 256>>>(h_d, W, out);
}

// round 15
// speedup vs baseline: 3.8111x; 1.2652x over previous
#include <cuda_runtime.h>
#include <cuda_fp16.h>
#include <cstdint>

#define NN 100000
#define NE 800000
#define NBLK 148
#define ET 512          // edge kernel threads (16 warps)

typedef unsigned long long u64;
typedef unsigned int u32;

// scratch (allocation-free rule: __device__ globals)
__device__ float g_agg[NN * 32];
__device__ u32 g_PH[NN * 32];           // fp16x2 fragment-major: [n][q*8 + nt] = (c0,c1)
__device__ u32 g_QH[NN * 32];
__device__ u64 g_B0s[512];              // L0 W0e frags, single fp16 (b0|b1)
__device__ u64 g_B1s[1024];             // L1 W1 frags, single fp16
__device__ u64 g_B2s[512];              // L2 W2 frags, single fp16
__device__ ulonglong2 g_BP[2048];       // precompute weight frags (P|Q halves), bf16 hi|lo

// ---------------- packed fp32x2 helpers (final kernel) ----------------
__device__ __forceinline__ u64 pack2(float x) {
    u64 r; asm("mov.b64 %0, {%1, %1};" : "=l"(r) : "f"(x)); return r;
}
__device__ __forceinline__ void ffma2(u64& d, u64 a, u64 b) {
    asm("fma.rn.f32x2 %0, %1, %2, %0;" : "+l"(d) : "l"(a), "l"(b));
}
__device__ __forceinline__ void rank1_16(float xf, const float* w16, u64* a0) {
    u64 xa = pack2(xf);
    const ulonglong2* wr = (const ulonglong2*)w16;
#pragma unroll
    for (int j = 0; j < 4; j++) {
        ulonglong2 w = wr[j];
        ffma2(a0[2 * j],     xa, w.x);
        ffma2(a0[2 * j + 1], xa, w.y);
    }
}

// ---------------- bf16 emulation helpers (pre_kernel path) ----------------
__device__ __forceinline__ u32 bf2pack(float x0, float x1) {
    u32 r;
    asm("cvt.rn.bf16x2.f32 %0, %1, %2;" : "=r"(r) : "f"(x1), "f"(x0));
    return r;
}
__device__ __forceinline__ void split_bf2(float x0, float x1, u32& h, u32& l) {
    h = bf2pack(x0, x1);
    float r0 = x0 - __uint_as_float(h << 16);
    float r1 = x1 - __uint_as_float(h & 0xFFFF0000u);
    l = bf2pack(r0, r1);
}
__device__ __forceinline__ void mma_bf(float c[4], const u32 a[4], u32 b0, u32 b1) {
    asm volatile(
        "mma.sync.aligned.m16n8k16.row.col.f32.bf16.bf16.f32 "
        "{%0,%1,%2,%3}, {%4,%5,%6,%7}, {%8,%9}, {%0,%1,%2,%3};"
        : "+f"(c[0]), "+f"(c[1]), "+f"(c[2]), "+f"(c[3])
        : "r"(a[0]), "r"(a[1]), "r"(a[2]), "r"(a[3]), "r"(b0), "r"(b1));
}
template <int NTC>
__device__ __forceinline__ void gemm_step_bf(float C[][4], const u32 ah[4], const u32 al[4],
                                             const ulonglong2* sB, int kc, int Kc, int lane) {
    u32 bh[NTC][2], bl[NTC][2];
#pragma unroll
    for (int nt = 0; nt < NTC; nt++) {
        ulonglong2 t = sB[(nt * Kc + kc) * 32 + lane];
        bh[nt][0] = (u32)t.x; bl[nt][0] = (u32)(t.x >> 32);
        bh[nt][1] = (u32)t.y; bl[nt][1] = (u32)(t.y >> 32);
    }
#pragma unroll
    for (int nt = 0; nt < NTC; nt++) mma_bf(C[nt], ah, bh[nt][0], bh[nt][1]);
#pragma unroll
    for (int nt = 0; nt < NTC; nt++) mma_bf(C[nt], ah, bl[nt][0], bl[nt][1]);
#pragma unroll
    for (int nt = 0; nt < NTC; nt++) mma_bf(C[nt], al, bh[nt][0], bh[nt][1]);
}

// ---------------- fp16 helpers (edge kernel path) ----------------
__device__ __forceinline__ u32 f16pack(float x0, float x1) {
    u32 r;
    asm("cvt.rn.f16x2.f32 %0, %1, %2;" : "=r"(r) : "f"(x1), "f"(x0));   // low = x0
    return r;
}
__device__ __forceinline__ float2 h2f(u32 v) {
    __half2 h = *(__half2*)&v;
    return __half22float2(h);
}
__device__ __forceinline__ void mma_f16(float c[4], const u32 a[4], u32 b0, u32 b1) {
    asm volatile(
        "mma.sync.aligned.m16n8k16.row.col.f32.f16.f16.f32 "
        "{%0,%1,%2,%3}, {%4,%5,%6,%7}, {%8,%9}, {%0,%1,%2,%3};"
        : "+f"(c[0]), "+f"(c[1]), "+f"(c[2]), "+f"(c[3])
        : "r"(a[0]), "r"(a[1]), "r"(a[2]), "r"(a[3]), "r"(b0), "r"(b1));
}
// 1-term K-chunk: C += A*B, single fp16 B
template <int NTC>
__device__ __forceinline__ void gemm_step1(float C[][4], const u32 a[4],
                                           const u64* sB, int kc, int Kc, int lane) {
    u64 t[NTC];
#pragma unroll
    for (int nt = 0; nt < NTC; nt++) t[nt] = sB[(nt * Kc + kc) * 32 + lane];
#pragma unroll
    for (int nt = 0; nt < NTC; nt++) mma_f16(C[nt], a, (u32)t[nt], (u32)(t[nt] >> 32));
}
__device__ __forceinline__ void build_a(const float cA[4], const float cB[4], u32 a[4]) {
    a[0] = f16pack(fmaxf(cA[0], 0.f), fmaxf(cA[1], 0.f));
    a[1] = f16pack(fmaxf(cA[2], 0.f), fmaxf(cA[3], 0.f));
    a[2] = f16pack(fmaxf(cB[0], 0.f), fmaxf(cB[1], 0.f));
    a[3] = f16pack(fmaxf(cB[2], 0.f), fmaxf(cB[3], 0.f));
}
__device__ __forceinline__ void red2(float* p, float x, float y) {
    asm volatile("red.global.add.v2.f32 [%0], {%1,%2};" :: "l"(p), "f"(x), "f"(y));
}

// ---------------- setup ----------------
// i<512: B0s; [512,1536): B1s; [1536,2048): B2s; [2048,4096): g_BP bf16 (pre).
__global__ void setup_kernel(const float* __restrict__ w0, const float* __restrict__ w1,
                             const float* __restrict__ w2) {
    int i = blockIdx.x * 256 + threadIdx.x;
    if (i >= 4096) return;
    int lane = i & 31;
    int g = lane >> 2, q = lane & 3;
    if (i < 512) {
        int f = i >> 5;                   // 0..15: nt = f>>1, kc = f&1
        int nt = f >> 1, kc = f & 1;
        int n = nt * 8 + g, k0 = 16 * kc + 2 * q;
        const float* W = w0 + 128 * 64;   // W0e, stride 64
        u32 b0 = f16pack(W[(size_t)k0 * 64 + n],       W[(size_t)(k0 + 1) * 64 + n]);
        u32 b1 = f16pack(W[(size_t)(k0 + 8) * 64 + n], W[(size_t)(k0 + 9) * 64 + n]);
        g_B0s[i] = (u64)b0 | ((u64)b1 << 32);
    } else if (i < 1536) {
        int j = i - 512;
        int f = j >> 5;                   // 0..31: nt = f>>2, kc = f&3
        int nt = f >> 2, kc = f & 3;
        int n = nt * 8 + g, k0 = 16 * kc + 2 * q;
        u32 b0 = f16pack(w1[(size_t)k0 * 64 + n],       w1[(size_t)(k0 + 1) * 64 + n]);
        u32 b1 = f16pack(w1[(size_t)(k0 + 8) * 64 + n], w1[(size_t)(k0 + 9) * 64 + n]);
        g_B1s[j] = (u64)b0 | ((u64)b1 << 32);
    } else if (i < 2048) {
        int j = i - 1536;
        int f = j >> 5;                   // 0..15: nt = f>>2, kc = f&3
        int nt = f >> 2, kc = f & 3;
        int n = nt * 8 + g, k0 = 16 * kc + 2 * q;
        u32 b0 = f16pack(w2[(size_t)k0 * 32 + n],       w2[(size_t)(k0 + 1) * 32 + n]);
        u32 b1 = f16pack(w2[(size_t)(k0 + 8) * 32 + n], w2[(size_t)(k0 + 9) * 32 + n]);
        g_B2s[j] = (u64)b0 | ((u64)b1 << 32);
    } else {
        int ff = (i - 2048) >> 5;
        int nt = ff >> 2, kc = ff & 3;
        int isq = (nt >= 8) ? 32 : 0;
        int nidx = (nt & 7) * 8 + g;
        int k0 = 16 * kc + 2 * q;
        int r00 = ((k0     < 32) ? k0     : k0 + 32) + isq;
        int r01 = ((k0 + 1 < 32) ? k0 + 1 : k0 + 33) + isq;
        int r10 = ((k0 + 8 < 32) ? k0 + 8 : k0 + 40) + isq;
        int r11 = ((k0 + 9 < 32) ? k0 + 9 : k0 + 41) + isq;
        u32 h0, l0, h1, l1;
        split_bf2(w0[(size_t)r00 * 64 + nidx], w0[(size_t)r01 * 64 + nidx], h0, l0);
        split_bf2(w0[(size_t)r10 * 64 + nidx], w0[(size_t)r11 * 64 + nidx], h1, l1);
        ulonglong2 t;
        t.x = (u64)h0 | ((u64)l0 << 32);
        t.y = (u64)h1 | ((u64)l1 << 32);
        g_BP[i - 2048] = t;
    }
}

// ---------------- precompute: P|Q = [h_s|h_d] @ W' via bf16-3term MMA; fp16 store; zeros g_agg ----------------
__global__ void __launch_bounds__(256, 1)
pre_kernel(const float* __restrict__ h_s, const float* __restrict__ h_d,
           const float* __restrict__ b0) {
    extern __shared__ ulonglong2 smem_v2[];
    float* s_b0 = (float*)(smem_v2 + 2048);
    const int tid = threadIdx.x, wid = tid >> 5, lane = tid & 31;
    const int g = lane >> 2, q = lane & 3;
    for (int i = tid; i < 2048; i += 256) smem_v2[i] = g_BP[i];
    if (tid < 64) s_b0[tid] = b0[tid];
    __syncthreads();

    int n0 = (blockIdx.x * 8 + wid) * 16;
    if (n0 >= NN) return;

    float C[16][4];
#pragma unroll
    for (int nt = 0; nt < 8; nt++) {
        C[nt][0] = 0.f; C[nt][1] = 0.f; C[nt][2] = 0.f; C[nt][3] = 0.f;
        float b0v = s_b0[nt * 8 + 2 * q], b1v = s_b0[nt * 8 + 2 * q + 1];
        C[8 + nt][0] = b0v; C[8 + nt][1] = b1v; C[8 + nt][2] = b0v; C[8 + nt][3] = b1v;
    }
#pragma unroll
    for (int kc = 0; kc < 4; kc++) {
        const float* src = (kc < 2) ? h_s : h_d;
        int off = (kc & 1) * 16 + 2 * q;
        float2 x0 = *(const float2*)(src + (size_t)(n0 + g) * 32 + off);
        float2 x1 = *(const float2*)(src + (size_t)(n0 + 8 + g) * 32 + off);
        float2 x2 = *(const float2*)(src + (size_t)(n0 + g) * 32 + off + 8);
        float2 x3 = *(const float2*)(src + (size_t)(n0 + 8 + g) * 32 + off + 8);
        u32 ah[4], al[4];
        split_bf2(x0.x, x0.y, ah[0], al[0]);
        split_bf2(x1.x, x1.y, ah[1], al[1]);
        split_bf2(x2.x, x2.y, ah[2], al[2]);
        split_bf2(x3.x, x3.y, ah[3], al[3]);
        gemm_step_bf<8>(C,     ah, al, smem_v2,           kc, 4, lane);   // P
        gemm_step_bf<8>(C + 8, ah, al, smem_v2 + 32 * 32, kc, 4, lane);   // Q
    }
    // pack to fp16x2, store fragment-major [n][q*8 + nt]
    {
        u32 vp0[8], vp1[8], vq0[8], vq1[8];
#pragma unroll
        for (int nt = 0; nt < 8; nt++) {
            vp0[nt] = f16pack(C[nt][0], C[nt][1]);
            vp1[nt] = f16pack(C[nt][2], C[nt][3]);
            vq0[nt] = f16pack(C[8+nt][0], C[8+nt][1]);
            vq1[nt] = f16pack(C[8+nt][2], C[8+nt][3]);
        }
        uint4* p = (uint4*)(g_PH + (size_t)(n0 + g) * 32 + q * 8);
        p[0] = make_uint4(vp0[0], vp0[1], vp0[2], vp0[3]);
        p[1] = make_uint4(vp0[4], vp0[5], vp0[6], vp0[7]);
        p = (uint4*)(g_PH + (size_t)(n0 + 8 + g) * 32 + q * 8);
        p[0] = make_uint4(vp1[0], vp1[1], vp1[2], vp1[3]);
        p[1] = make_uint4(vp1[4], vp1[5], vp1[6], vp1[7]);
        p = (uint4*)(g_QH + (size_t)(n0 + g) * 32 + q * 8);
        p[0] = make_uint4(vq0[0], vq0[1], vq0[2], vq0[3]);
        p[1] = make_uint4(vq0[4], vq0[5], vq0[6], vq0[7]);
        p = (uint4*)(g_QH + (size_t)(n0 + 8 + g) * 32 + q * 8);
        p[0] = make_uint4(vq1[0], vq1[1], vq1[2], vq1[3]);
        p[1] = make_uint4(vq1[4], vq1[5], vq1[6], vq1[7]);
    }
    float4 z = make_float4(0.f, 0.f, 0.f, 0.f);
    float4* ag = (float4*)(g_agg + (size_t)n0 * 32);
#pragma unroll
    for (int i = 0; i < 4; i++) ag[lane + 32 * i] = z;
}

// ---------------- edge kernel: fp16 1-term MMA MLP, fp16 P/Q gathers ----------------
// smem: sB0s u64[512] @0 (4KB), sB1s u64[1024] @4096 (8KB), sB2s u64[512] @12288 (4KB),
//       biases @16384
#define SMEM_BYTES (16384 + 96 * 4)

__global__ void __launch_bounds__(ET, 1)
edge_kernel(const float* __restrict__ h_d, const float* __restrict__ ef,
            const int* __restrict__ si, const int* __restrict__ ri,
            const float* __restrict__ b1, const float* __restrict__ b2) {
    extern __shared__ char smem_c[];
    u64* sB0s = (u64*)smem_c;
    u64* sB1s = (u64*)(smem_c + 4096);
    u64* sB2s = (u64*)(smem_c + 12288);
    float* s_b1 = (float*)(smem_c + 16384);
    float* s_b2 = s_b1 + 64;

    const int tid = threadIdx.x, wid = tid >> 5, lane = tid & 31;
    for (int i = tid; i < 512; i += ET) sB0s[i] = g_B0s[i];
    for (int i = tid; i < 1024; i += ET) sB1s[i] = g_B1s[i];
    for (int i = tid; i < 512; i += ET) sB2s[i] = g_B2s[i];
    if (tid < 64) s_b1[tid] = b1[tid];
    if (tid < 32) s_b2[tid] = b2[tid];
    __syncthreads();

    const int g = lane >> 2, q = lane & 3;
    const int col2 = 2 * q;
    const int WPC = ET / 32;

#pragma unroll 1
    for (int base = blockIdx.x * (WPC * 16) + wid * 16; base < NE; base += NBLK * (WPC * 16)) {
        int e0 = base + g, e1 = base + 8 + g;
        bool v0 = e0 < NE, v1 = e1 < NE;
        int e0c = v0 ? e0 : NE - 1;
        int e1c = v1 ? e1 : NE - 1;
        int s0 = si[e0c], rc0 = ri[e0c];
        int s1 = si[e1c], rc1 = ri[e1c];

        // ===== layer 0: C init from P[s]+Q[r] (fp16x2 gathers, fp32 adds) =====
        float C[8][4];
        {
            const uint4* P0 = (const uint4*)(g_PH + (size_t)s0  * 32 + q * 8);
            const uint4* Q0 = (const uint4*)(g_QH + (size_t)rc0 * 32 + q * 8);
            const uint4* P1 = (const uint4*)(g_PH + (size_t)s1  * 32 + q * 8);
            const uint4* Q1 = (const uint4*)(g_QH + (size_t)rc1 * 32 + q * 8);
            uint4 pa0 = P0[0], pa1 = P0[1], qa0 = Q0[0], qa1 = Q0[1];
            uint4 pb0 = P1[0], pb1 = P1[1], qb0 = Q1[0], qb1 = Q1[1];
            u32 pv0[8] = {pa0.x, pa0.y, pa0.z, pa0.w, pa1.x, pa1.y, pa1.z, pa1.w};
            u32 qv0[8] = {qa0.x, qa0.y, qa0.z, qa0.w, qa1.x, qa1.y, qa1.z, qa1.w};
            u32 pv1[8] = {pb0.x, pb0.y, pb0.z, pb0.w, pb1.x, pb1.y, pb1.z, pb1.w};
            u32 qv1[8] = {qb0.x, qb0.y, qb0.z, qb0.w, qb1.x, qb1.y, qb1.z, qb1.w};
#pragma unroll
            for (int nt = 0; nt < 8; nt++) {
                float2 a = h2f(pv0[nt]), b = h2f(qv0[nt]);
                C[nt][0] = a.x + b.x; C[nt][1] = a.y + b.y;
                a = h2f(pv1[nt]); b = h2f(qv1[nt]);
                C[nt][2] = a.x + b.x; C[nt][3] = a.y + b.y;
            }
        }
        // ===== layer 0: += ef @ W0e (1-term) =====
#pragma unroll
        for (int kc = 0; kc < 2; kc++) {
            int off = 16 * kc + col2;
            float2 x0 = *(const float2*)(ef + (size_t)e0c * 32 + off);
            float2 x1 = *(const float2*)(ef + (size_t)e1c * 32 + off);
            float2 x2 = *(const float2*)(ef + (size_t)e0c * 32 + off + 8);
            float2 x3 = *(const float2*)(ef + (size_t)e1c * 32 + off + 8);
            u32 a[4];
            a[0] = f16pack(x0.x, x0.y);
            a[1] = f16pack(x1.x, x1.y);
            a[2] = f16pack(x2.x, x2.y);
            a[3] = f16pack(x3.x, x3.y);
            gemm_step1<8>(C, a, sB0s, kc, 2, lane);
        }

        // ===== layer 1 (1-term) =====
        float C1[8][4];
#pragma unroll
        for (int nt = 0; nt < 8; nt++) {
            float bb0 = s_b1[nt * 8 + col2], bb1 = s_b1[nt * 8 + col2 + 1];
            C1[nt][0] = bb0; C1[nt][1] = bb1; C1[nt][2] = bb0; C1[nt][3] = bb1;
        }
#pragma unroll
        for (int kc = 0; kc < 4; kc++) {
            u32 a[4];
            build_a(C[2 * kc], C[2 * kc + 1], a);
            gemm_step1<8>(C1, a, sB1s, kc, 4, lane);
        }

        // ===== layer 2 (1-term) =====
        float C2[4][4];
#pragma unroll
        for (int nt = 0; nt < 4; nt++) {
            float bb0 = s_b2[nt * 8 + col2], bb1 = s_b2[nt * 8 + col2 + 1];
            C2[nt][0] = bb0; C2[nt][1] = bb1; C2[nt][2] = bb0; C2[nt][3] = bb1;
        }
#pragma unroll
        for (int kc = 0; kc < 4; kc++) {
            u32 a[4];
            build_a(C1[2 * kc], C1[2 * kc + 1], a);
            gemm_step1<4>(C2, a, sB2s, kc, 4, lane);
        }

        // ===== epilogue: relu(psi) * (h_dj - h_di), vector scatter-add =====
#pragma unroll
        for (int nt = 0; nt < 4; nt++) {
            int cc = nt * 8 + col2;
            if (v0) {
                float2 dj = *(const float2*)(h_d + (size_t)rc0 * 32 + cc);
                float2 di = *(const float2*)(h_d + (size_t)s0 * 32 + cc);
                red2(g_agg + (size_t)rc0 * 32 + cc,
                     fmaxf(C2[nt][0], 0.f) * (dj.x - di.x),
                     fmaxf(C2[nt][1], 0.f) * (dj.y - di.y));
            }
            if (v1) {
                float2 dj = *(const float2*)(h_d + (size_t)rc1 * 32 + cc);
                float2 di = *(const float2*)(h_d + (size_t)s1 * 32 + cc);
                red2(g_agg + (size_t)rc1 * 32 + cc,
                     fmaxf(C2[nt][2], 0.f) * (dj.x - di.x),
                     fmaxf(C2[nt][3], 0.f) * (dj.y - di.y));
            }
        }
    }
}

// out[n] = h_d_prev[n] + agg[n] @ W   (2 threads per node, 16 outputs each)
__global__ void __launch_bounds__(256)
final_kernel(const float* __restrict__ h_d, const float* __restrict__ W,
             float* __restrict__ out) {
    __shared__ float sW[1024];
    int tid = threadIdx.x;
    {
        float4* d4 = (float4*)sW;
        const float4* s4 = (const float4*)W;
        for (int i = tid; i < 256; i += 256) d4[i] = s4[i];
    }
    __syncthreads();
    int idx = blockIdx.x * 256 + tid;
    int n = idx >> 1, half = idx & 1;
    if (n >= NN) return;

    u64 acc[8];
    {
        const ulonglong2* hp = (const ulonglong2*)(h_d + (size_t)n * 32 + half * 16);
#pragma unroll
        for (int j = 0; j < 4; j++) {
            ulonglong2 t = hp[j];
            acc[2 * j] = t.x; acc[2 * j + 1] = t.y;
        }
    }
    const float4* ap = (const float4*)(g_agg + (size_t)n * 32);
    const float* wb = sW + half * 16;
#pragma unroll
    for (int i = 0; i < 8; i++) {
        float4 a = ap[i];
        rank1_16(a.x, wb + (4 * i) * 32,     acc);
        rank1_16(a.y, wb + (4 * i + 1) * 32, acc);
        rank1_16(a.z, wb + (4 * i + 2) * 32, acc);
        rank1_16(a.w, wb + (4 * i + 3) * 32, acc);
    }
    ulonglong2* op = (ulonglong2*)(out + (size_t)n * 32 + half * 16);
#pragma unroll
    for (int j = 0; j < 4; j++) {
        ulonglong2 t; t.x = acc[2 * j]; t.y = acc[2 * j + 1];
        op[j] = t;
    }
}

extern "C" void kernel_launch(void* const* d_in, const int* in_sizes, int n_in,
                              void* d_out, int out_size) {
    const float* h_d = (const float*)d_in[0];
    const float* h_s = (const float*)d_in[1];
    const float* ef  = (const float*)d_in[2];
    const int*   si  = (const int*)d_in[3];
    const int*   ri  = (const int*)d_in[4];
    const float* w0  = (const float*)d_in[5];
    const float* b0  = (const float*)d_in[6];
    const float* w1  = (const float*)d_in[7];
    const float* b1  = (const float*)d_in[8];
    const float* w2  = (const float*)d_in[9];
    const float* b2  = (const float*)d_in[10];
    const float* W   = (const float*)d_in[11];
    float* out = (float*)d_out;

    cudaFuncSetAttribute(edge_kernel, cudaFuncAttributeMaxDynamicSharedMemorySize,
                         SMEM_BYTES);
    cudaFuncSetAttribute(pre_kernel, cudaFuncAttributeMaxDynamicSharedMemorySize,
                         2048 * 16 + 64 * 4);

    setup_kernel<<<16, 256>>>(w0, w1, w2);
    pre_kernel<<<782, 256, 2048 * 16 + 64 * 4>>>(h_s, h_d, b0);
    edge_kernel<<<NBLK, ET, SMEM_BYTES>>>(h_d, ef, si, ri, b1, b2);
    final_kernel<<<(2 * NN + 255) / 256, 256>>>(h_d, W, out);
}

// round 16
// speedup vs baseline: 4.5630x; 1.1973x over previous
#include <cuda_runtime.h>
#include <cuda_fp16.h>
#include <cstdint>

#define NN 100000
#define NE 800000
#define NBLK 148
#define ET 512          // edge kernel threads (16 warps)

typedef unsigned long long u64;
typedef unsigned int u32;

// scratch (allocation-free rule: __device__ globals)
__device__ float g_agg[NN * 32];
__device__ u32 g_PH[NN * 32];           // fp16x2 fragment-major: [n][q*8 + nt] = (c0,c1)
__device__ u32 g_QH[NN * 32];
__device__ u32 g_HD[NN * 16];           // fp16x2 h_d epilogue-major: [n][q*4 + nt] = cols (nt*8+2q, +1)
__device__ u64 g_B0s[512];              // L0 W0e frags, single fp16 (b0|b1)
__device__ u64 g_B1s[1024];             // L1 W1 frags, single fp16
__device__ u64 g_B2s[512];              // L2 W2 frags, single fp16
__device__ ulonglong2 g_BP[2048];       // precompute weight frags (P|Q halves), bf16 hi|lo

// ---------------- packed fp32x2 helpers (final kernel) ----------------
__device__ __forceinline__ u64 pack2(float x) {
    u64 r; asm("mov.b64 %0, {%1, %1};" : "=l"(r) : "f"(x)); return r;
}
__device__ __forceinline__ void ffma2(u64& d, u64 a, u64 b) {
    asm("fma.rn.f32x2 %0, %1, %2, %0;" : "+l"(d) : "l"(a), "l"(b));
}
__device__ __forceinline__ void rank1_16(float xf, const float* w16, u64* a0) {
    u64 xa = pack2(xf);
    const ulonglong2* wr = (const ulonglong2*)w16;
#pragma unroll
    for (int j = 0; j < 4; j++) {
        ulonglong2 w = wr[j];
        ffma2(a0[2 * j],     xa, w.x);
        ffma2(a0[2 * j + 1], xa, w.y);
    }
}

// ---------------- bf16 emulation helpers (pre_kernel path) ----------------
__device__ __forceinline__ u32 bf2pack(float x0, float x1) {
    u32 r;
    asm("cvt.rn.bf16x2.f32 %0, %1, %2;" : "=r"(r) : "f"(x1), "f"(x0));
    return r;
}
__device__ __forceinline__ void split_bf2(float x0, float x1, u32& h, u32& l) {
    h = bf2pack(x0, x1);
    float r0 = x0 - __uint_as_float(h << 16);
    float r1 = x1 - __uint_as_float(h & 0xFFFF0000u);
    l = bf2pack(r0, r1);
}
__device__ __forceinline__ void mma_bf(float c[4], const u32 a[4], u32 b0, u32 b1) {
    asm volatile(
        "mma.sync.aligned.m16n8k16.row.col.f32.bf16.bf16.f32 "
        "{%0,%1,%2,%3}, {%4,%5,%6,%7}, {%8,%9}, {%0,%1,%2,%3};"
        : "+f"(c[0]), "+f"(c[1]), "+f"(c[2]), "+f"(c[3])
        : "r"(a[0]), "r"(a[1]), "r"(a[2]), "r"(a[3]), "r"(b0), "r"(b1));
}
template <int NTC>
__device__ __forceinline__ void gemm_step_bf(float C[][4], const u32 ah[4], const u32 al[4],
                                             const ulonglong2* sB, int kc, int Kc, int lane) {
    u32 bh[NTC][2], bl[NTC][2];
#pragma unroll
    for (int nt = 0; nt < NTC; nt++) {
        ulonglong2 t = sB[(nt * Kc + kc) * 32 + lane];
        bh[nt][0] = (u32)t.x; bl[nt][0] = (u32)(t.x >> 32);
        bh[nt][1] = (u32)t.y; bl[nt][1] = (u32)(t.y >> 32);
    }
#pragma unroll
    for (int nt = 0; nt < NTC; nt++) mma_bf(C[nt], ah, bh[nt][0], bh[nt][1]);
#pragma unroll
    for (int nt = 0; nt < NTC; nt++) mma_bf(C[nt], ah, bl[nt][0], bl[nt][1]);
#pragma unroll
    for (int nt = 0; nt < NTC; nt++) mma_bf(C[nt], al, bh[nt][0], bh[nt][1]);
}

// ---------------- fp16 helpers (edge kernel path) ----------------
__device__ __forceinline__ u32 f16pack(float x0, float x1) {
    u32 r;
    asm("cvt.rn.f16x2.f32 %0, %1, %2;" : "=r"(r) : "f"(x1), "f"(x0));   // low = x0
    return r;
}
__device__ __forceinline__ float2 h2f(u32 v) {
    __half2 h = *(__half2*)&v;
    return __half22float2(h);
}
__device__ __forceinline__ void mma_f16(float c[4], const u32 a[4], u32 b0, u32 b1) {
    asm volatile(
        "mma.sync.aligned.m16n8k16.row.col.f32.f16.f16.f32 "
        "{%0,%1,%2,%3}, {%4,%5,%6,%7}, {%8,%9}, {%0,%1,%2,%3};"
        : "+f"(c[0]), "+f"(c[1]), "+f"(c[2]), "+f"(c[3])
        : "r"(a[0]), "r"(a[1]), "r"(a[2]), "r"(a[3]), "r"(b0), "r"(b1));
}
// 1-term K-chunk: C += A*B, single fp16 B
template <int NTC>
__device__ __forceinline__ void gemm_step1(float C[][4], const u32 a[4],
                                           const u64* sB, int kc, int Kc, int lane) {
    u64 t[NTC];
#pragma unroll
    for (int nt = 0; nt < NTC; nt++) t[nt] = sB[(nt * Kc + kc) * 32 + lane];
#pragma unroll
    for (int nt = 0; nt < NTC; nt++) mma_f16(C[nt], a, (u32)t[nt], (u32)(t[nt] >> 32));
}
__device__ __forceinline__ void build_a(const float cA[4], const float cB[4], u32 a[4]) {
    a[0] = f16pack(fmaxf(cA[0], 0.f), fmaxf(cA[1], 0.f));
    a[1] = f16pack(fmaxf(cA[2], 0.f), fmaxf(cA[3], 0.f));
    a[2] = f16pack(fmaxf(cB[0], 0.f), fmaxf(cB[1], 0.f));
    a[3] = f16pack(fmaxf(cB[2], 0.f), fmaxf(cB[3], 0.f));
}
__device__ __forceinline__ void red2(float* p, float x, float y) {
    asm volatile("red.global.add.v2.f32 [%0], {%1,%2};" :: "l"(p), "f"(x), "f"(y));
}

// ---------------- setup ----------------
// i<512: B0s; [512,1536): B1s; [1536,2048): B2s; [2048,4096): g_BP bf16 (pre).
__global__ void setup_kernel(const float* __restrict__ w0, const float* __restrict__ w1,
                             const float* __restrict__ w2) {
    int i = blockIdx.x * 256 + threadIdx.x;
    if (i >= 4096) return;
    int lane = i & 31;
    int g = lane >> 2, q = lane & 3;
    if (i < 512) {
        int f = i >> 5;                   // 0..15: nt = f>>1, kc = f&1
        int nt = f >> 1, kc = f & 1;
        int n = nt * 8 + g, k0 = 16 * kc + 2 * q;
        const float* W = w0 + 128 * 64;   // W0e, stride 64
        u32 b0 = f16pack(W[(size_t)k0 * 64 + n],       W[(size_t)(k0 + 1) * 64 + n]);
        u32 b1 = f16pack(W[(size_t)(k0 + 8) * 64 + n], W[(size_t)(k0 + 9) * 64 + n]);
        g_B0s[i] = (u64)b0 | ((u64)b1 << 32);
    } else if (i < 1536) {
        int j = i - 512;
        int f = j >> 5;                   // 0..31: nt = f>>2, kc = f&3
        int nt = f >> 2, kc = f & 3;
        int n = nt * 8 + g, k0 = 16 * kc + 2 * q;
        u32 b0 = f16pack(w1[(size_t)k0 * 64 + n],       w1[(size_t)(k0 + 1) * 64 + n]);
        u32 b1 = f16pack(w1[(size_t)(k0 + 8) * 64 + n], w1[(size_t)(k0 + 9) * 64 + n]);
        g_B1s[j] = (u64)b0 | ((u64)b1 << 32);
    } else if (i < 2048) {
        int j = i - 1536;
        int f = j >> 5;                   // 0..15: nt = f>>2, kc = f&3
        int nt = f >> 2, kc = f & 3;
        int n = nt * 8 + g, k0 = 16 * kc + 2 * q;
        u32 b0 = f16pack(w2[(size_t)k0 * 32 + n],       w2[(size_t)(k0 + 1) * 32 + n]);
        u32 b1 = f16pack(w2[(size_t)(k0 + 8) * 32 + n], w2[(size_t)(k0 + 9) * 32 + n]);
        g_B2s[j] = (u64)b0 | ((u64)b1 << 32);
    } else {
        int ff = (i - 2048) >> 5;
        int nt = ff >> 2, kc = ff & 3;
        int isq = (nt >= 8) ? 32 : 0;
        int nidx = (nt & 7) * 8 + g;
        int k0 = 16 * kc + 2 * q;
        int r00 = ((k0     < 32) ? k0     : k0 + 32) + isq;
        int r01 = ((k0 + 1 < 32) ? k0 + 1 : k0 + 33) + isq;
        int r10 = ((k0 + 8 < 32) ? k0 + 8 : k0 + 40) + isq;
        int r11 = ((k0 + 9 < 32) ? k0 + 9 : k0 + 41) + isq;
        u32 h0, l0, h1, l1;
        split_bf2(w0[(size_t)r00 * 64 + nidx], w0[(size_t)r01 * 64 + nidx], h0, l0);
        split_bf2(w0[(size_t)r10 * 64 + nidx], w0[(size_t)r11 * 64 + nidx], h1, l1);
        ulonglong2 t;
        t.x = (u64)h0 | ((u64)l0 << 32);
        t.y = (u64)h1 | ((u64)l1 << 32);
        g_BP[i - 2048] = t;
    }
}

// ---------------- precompute: P|Q tables (fp16), h_d fp16 table; zeros g_agg ----------------
__global__ void __launch_bounds__(256, 1)
pre_kernel(const float* __restrict__ h_s, const float* __restrict__ h_d,
           const float* __restrict__ b0) {
    extern __shared__ ulonglong2 smem_v2[];
    float* s_b0 = (float*)(smem_v2 + 2048);
    const int tid = threadIdx.x, wid = tid >> 5, lane = tid & 31;
    const int g = lane >> 2, q = lane & 3;
    for (int i = tid; i < 2048; i += 256) smem_v2[i] = g_BP[i];
    if (tid < 64) s_b0[tid] = b0[tid];
    __syncthreads();

    int n0 = (blockIdx.x * 8 + wid) * 16;
    if (n0 >= NN) return;

    float C[16][4];
#pragma unroll
    for (int nt = 0; nt < 8; nt++) {
        C[nt][0] = 0.f; C[nt][1] = 0.f; C[nt][2] = 0.f; C[nt][3] = 0.f;
        float b0v = s_b0[nt * 8 + 2 * q], b1v = s_b0[nt * 8 + 2 * q + 1];
        C[8 + nt][0] = b0v; C[8 + nt][1] = b1v; C[8 + nt][2] = b0v; C[8 + nt][3] = b1v;
    }
#pragma unroll
    for (int kc = 0; kc < 4; kc++) {
        const float* src = (kc < 2) ? h_s : h_d;
        int off = (kc & 1) * 16 + 2 * q;
        float2 x0 = *(const float2*)(src + (size_t)(n0 + g) * 32 + off);
        float2 x1 = *(const float2*)(src + (size_t)(n0 + 8 + g) * 32 + off);
        float2 x2 = *(const float2*)(src + (size_t)(n0 + g) * 32 + off + 8);
        float2 x3 = *(const float2*)(src + (size_t)(n0 + 8 + g) * 32 + off + 8);
        u32 ah[4], al[4];
        split_bf2(x0.x, x0.y, ah[0], al[0]);
        split_bf2(x1.x, x1.y, ah[1], al[1]);
        split_bf2(x2.x, x2.y, ah[2], al[2]);
        split_bf2(x3.x, x3.y, ah[3], al[3]);
        gemm_step_bf<8>(C,     ah, al, smem_v2,           kc, 4, lane);   // P
        gemm_step_bf<8>(C + 8, ah, al, smem_v2 + 32 * 32, kc, 4, lane);   // Q
    }
    // pack P/Q to fp16x2, store fragment-major [n][q*8 + nt]
    {
        u32 vp0[8], vp1[8], vq0[8], vq1[8];
#pragma unroll
        for (int nt = 0; nt < 8; nt++) {
            vp0[nt] = f16pack(C[nt][0], C[nt][1]);
            vp1[nt] = f16pack(C[nt][2], C[nt][3]);
            vq0[nt] = f16pack(C[8+nt][0], C[8+nt][1]);
            vq1[nt] = f16pack(C[8+nt][2], C[8+nt][3]);
        }
        uint4* p = (uint4*)(g_PH + (size_t)(n0 + g) * 32 + q * 8);
        p[0] = make_uint4(vp0[0], vp0[1], vp0[2], vp0[3]);
        p[1] = make_uint4(vp0[4], vp0[5], vp0[6], vp0[7]);
        p = (uint4*)(g_PH + (size_t)(n0 + 8 + g) * 32 + q * 8);
        p[0] = make_uint4(vp1[0], vp1[1], vp1[2], vp1[3]);
        p[1] = make_uint4(vp1[4], vp1[5], vp1[6], vp1[7]);
        p = (uint4*)(g_QH + (size_t)(n0 + g) * 32 + q * 8);
        p[0] = make_uint4(vq0[0], vq0[1], vq0[2], vq0[3]);
        p[1] = make_uint4(vq0[4], vq0[5], vq0[6], vq0[7]);
        p = (uint4*)(g_QH + (size_t)(n0 + 8 + g) * 32 + q * 8);
        p[0] = make_uint4(vq1[0], vq1[1], vq1[2], vq1[3]);
        p[1] = make_uint4(vq1[4], vq1[5], vq1[6], vq1[7]);
    }
    // h_d fp16 epilogue table: [n][q*4 + nt] = cols (nt*8+2q, +1)
    {
#pragma unroll
        for (int rsel = 0; rsel < 2; rsel++) {
            int n = n0 + rsel * 8 + g;
            u32 v[4];
#pragma unroll
            for (int nt = 0; nt < 4; nt++) {
                float2 x = *(const float2*)(h_d + (size_t)n * 32 + nt * 8 + 2 * q);
                v[nt] = f16pack(x.x, x.y);
            }
            *(uint4*)(g_HD + (size_t)n * 16 + q * 4) = make_uint4(v[0], v[1], v[2], v[3]);
        }
    }
    float4 z = make_float4(0.f, 0.f, 0.f, 0.f);
    float4* ag = (float4*)(g_agg + (size_t)n0 * 32);
#pragma unroll
    for (int i = 0; i < 4; i++) ag[lane + 32 * i] = z;
}

// ---------------- edge kernel: fp16 1-term MMA MLP, all-fp16 gathers ----------------
// smem: sB0s u64[512] @0 (4KB), sB1s u64[1024] @4096 (8KB), sB2s u64[512] @12288 (4KB),
//       biases @16384
#define SMEM_BYTES (16384 + 96 * 4)

__global__ void __launch_bounds__(ET, 1)
edge_kernel(const float* __restrict__ ef,
            const int* __restrict__ si, const int* __restrict__ ri,
            const float* __restrict__ b1, const float* __restrict__ b2) {
    extern __shared__ char smem_c[];
    u64* sB0s = (u64*)smem_c;
    u64* sB1s = (u64*)(smem_c + 4096);
    u64* sB2s = (u64*)(smem_c + 12288);
    float* s_b1 = (float*)(smem_c + 16384);
    float* s_b2 = s_b1 + 64;

    const int tid = threadIdx.x, wid = tid >> 5, lane = tid & 31;
    for (int i = tid; i < 512; i += ET) sB0s[i] = g_B0s[i];
    for (int i = tid; i < 1024; i += ET) sB1s[i] = g_B1s[i];
    for (int i = tid; i < 512; i += ET) sB2s[i] = g_B2s[i];
    if (tid < 64) s_b1[tid] = b1[tid];
    if (tid < 32) s_b2[tid] = b2[tid];
    __syncthreads();

    const int g = lane >> 2, q = lane & 3;
    const int col2 = 2 * q;
    const int WPC = ET / 32;

#pragma unroll 1
    for (int base = blockIdx.x * (WPC * 16) + wid * 16; base < NE; base += NBLK * (WPC * 16)) {
        int e0 = base + g, e1 = base + 8 + g;
        bool v0 = e0 < NE, v1 = e1 < NE;
        int e0c = v0 ? e0 : NE - 1;
        int e1c = v1 ? e1 : NE - 1;
        int s0 = si[e0c], rc0 = ri[e0c];
        int s1 = si[e1c], rc1 = ri[e1c];

        // ===== layer 0: C init from P[s]+Q[r] (fp16x2 gathers, fp32 adds) =====
        float C[8][4];
        {
            const uint4* P0 = (const uint4*)(g_PH + (size_t)s0  * 32 + q * 8);
            const uint4* Q0 = (const uint4*)(g_QH + (size_t)rc0 * 32 + q * 8);
            const uint4* P1 = (const uint4*)(g_PH + (size_t)s1  * 32 + q * 8);
            const uint4* Q1 = (const uint4*)(g_QH + (size_t)rc1 * 32 + q * 8);
            uint4 pa0 = P0[0], pa1 = P0[1], qa0 = Q0[0], qa1 = Q0[1];
            uint4 pb0 = P1[0], pb1 = P1[1], qb0 = Q1[0], qb1 = Q1[1];
            u32 pv0[8] = {pa0.x, pa0.y, pa0.z, pa0.w, pa1.x, pa1.y, pa1.z, pa1.w};
            u32 qv0[8] = {qa0.x, qa0.y, qa0.z, qa0.w, qa1.x, qa1.y, qa1.z, qa1.w};
            u32 pv1[8] = {pb0.x, pb0.y, pb0.z, pb0.w, pb1.x, pb1.y, pb1.z, pb1.w};
            u32 qv1[8] = {qb0.x, qb0.y, qb0.z, qb0.w, qb1.x, qb1.y, qb1.z, qb1.w};
#pragma unroll
            for (int nt = 0; nt < 8; nt++) {
                float2 a = h2f(pv0[nt]), b = h2f(qv0[nt]);
                C[nt][0] = a.x + b.x; C[nt][1] = a.y + b.y;
                a = h2f(pv1[nt]); b = h2f(qv1[nt]);
                C[nt][2] = a.x + b.x; C[nt][3] = a.y + b.y;
            }
        }
        // ===== layer 0: += ef @ W0e (1-term) =====
#pragma unroll
        for (int kc = 0; kc < 2; kc++) {
            int off = 16 * kc + col2;
            float2 x0 = *(const float2*)(ef + (size_t)e0c * 32 + off);
            float2 x1 = *(const float2*)(ef + (size_t)e1c * 32 + off);
            float2 x2 = *(const float2*)(ef + (size_t)e0c * 32 + off + 8);
            float2 x3 = *(const float2*)(ef + (size_t)e1c * 32 + off + 8);
            u32 a[4];
            a[0] = f16pack(x0.x, x0.y);
            a[1] = f16pack(x1.x, x1.y);
            a[2] = f16pack(x2.x, x2.y);
            a[3] = f16pack(x3.x, x3.y);
            gemm_step1<8>(C, a, sB0s, kc, 2, lane);
        }

        // ===== layer 1 (1-term) =====
        float C1[8][4];
#pragma unroll
        for (int nt = 0; nt < 8; nt++) {
            float bb0 = s_b1[nt * 8 + col2], bb1 = s_b1[nt * 8 + col2 + 1];
            C1[nt][0] = bb0; C1[nt][1] = bb1; C1[nt][2] = bb0; C1[nt][3] = bb1;
        }
#pragma unroll
        for (int kc = 0; kc < 4; kc++) {
            u32 a[4];
            build_a(C[2 * kc], C[2 * kc + 1], a);
            gemm_step1<8>(C1, a, sB1s, kc, 4, lane);
        }

        // ===== layer 2 (1-term) =====
        float C2[4][4];
#pragma unroll
        for (int nt = 0; nt < 4; nt++) {
            float bb0 = s_b2[nt * 8 + col2], bb1 = s_b2[nt * 8 + col2 + 1];
            C2[nt][0] = bb0; C2[nt][1] = bb1; C2[nt][2] = bb0; C2[nt][3] = bb1;
        }
#pragma unroll
        for (int kc = 0; kc < 4; kc++) {
            u32 a[4];
            build_a(C1[2 * kc], C1[2 * kc + 1], a);
            gemm_step1<4>(C2, a, sB2s, kc, 4, lane);
        }

        // ===== epilogue: relu(psi) * (h_dj - h_di), fp16 h_d gathers =====
        {
            uint4 dj0 = *(const uint4*)(g_HD + (size_t)rc0 * 16 + q * 4);
            uint4 di0 = *(const uint4*)(g_HD + (size_t)s0  * 16 + q * 4);
            uint4 dj1 = *(const uint4*)(g_HD + (size_t)rc1 * 16 + q * 4);
            uint4 di1 = *(const uint4*)(g_HD + (size_t)s1  * 16 + q * 4);
            u32 j0[4] = {dj0.x, dj0.y, dj0.z, dj0.w};
            u32 i0[4] = {di0.x, di0.y, di0.z, di0.w};
            u32 j1[4] = {dj1.x, dj1.y, dj1.z, dj1.w};
            u32 i1[4] = {di1.x, di1.y, di1.z, di1.w};
#pragma unroll
            for (int nt = 0; nt < 4; nt++) {
                int cc = nt * 8 + col2;
                if (v0) {
                    float2 a = h2f(j0[nt]), b = h2f(i0[nt]);
                    red2(g_agg + (size_t)rc0 * 32 + cc,
                         fmaxf(C2[nt][0], 0.f) * (a.x - b.x),
                         fmaxf(C2[nt][1], 0.f) * (a.y - b.y));
                }
                if (v1) {
                    float2 a = h2f(j1[nt]), b = h2f(i1[nt]);
                    red2(g_agg + (size_t)rc1 * 32 + cc,
                         fmaxf(C2[nt][2], 0.f) * (a.x - b.x),
                         fmaxf(C2[nt][3], 0.f) * (a.y - b.y));
                }
            }
        }
    }
}

// out[n] = h_d_prev[n] + agg[n] @ W   (2 threads per node, 16 outputs each)
__global__ void __launch_bounds__(256)
final_kernel(const float* __restrict__ h_d, const float* __restrict__ W,
             float* __restrict__ out) {
    __shared__ float sW[1024];
    int tid = threadIdx.x;
    {
        float4* d4 = (float4*)sW;
        const float4* s4 = (const float4*)W;
        for (int i = tid; i < 256; i += 256) d4[i] = s4[i];
    }
    __syncthreads();
    int idx = blockIdx.x * 256 + tid;
    int n = idx >> 1, half = idx & 1;
    if (n >= NN) return;

    u64 acc[8];
    {
        const ulonglong2* hp = (const ulonglong2*)(h_d + (size_t)n * 32 + half * 16);
#pragma unroll
        for (int j = 0; j < 4; j++) {
            ulonglong2 t = hp[j];
            acc[2 * j] = t.x; acc[2 * j + 1] = t.y;
        }
    }
    const float4* ap = (const float4*)(g_agg + (size_t)n * 32);
    const float* wb = sW + half * 16;
#pragma unroll
    for (int i = 0; i < 8; i++) {
        float4 a = ap[i];
        rank1_16(a.x, wb + (4 * i) * 32,     acc);
        rank1_16(a.y, wb + (4 * i + 1) * 32, acc);
        rank1_16(a.z, wb + (4 * i + 2) * 32, acc);
        rank1_16(a.w, wb + (4 * i + 3) * 32, acc);
    }
    ulonglong2* op = (ulonglong2*)(out + (size_t)n * 32 + half * 16);
#pragma unroll
    for (int j = 0; j < 4; j++) {
        ulonglong2 t; t.x = acc[2 * j]; t.y = acc[2 * j + 1];
        op[j] = t;
    }
}

extern "C" void kernel_launch(void* const* d_in, const int* in_sizes, int n_in,
                              void* d_out, int out_size) {
    const float* h_d = (const float*)d_in[0];
    const float* h_s = (const float*)d_in[1];
    const float* ef  = (const float*)d_in[2];
    const int*   si  = (const int*)d_in[3];
    const int*   ri  = (const int*)d_in[4];
    const float* w0  = (const float*)d_in[5];
    const float* b0  = (const float*)d_in[6];
    const float* w1  = (const float*)d_in[7];
    const float* b1  = (const float*)d_in[8];
    const float* w2  = (const float*)d_in[9];
    const float* b2  = (const float*)d_in[10];
    const float* W   = (const float*)d_in[11];
    float* out = (float*)d_out;

    cudaFuncSetAttribute(edge_kernel, cudaFuncAttributeMaxDynamicSharedMemorySize,
                         SMEM_BYTES);
    cudaFuncSetAttribute(pre_kernel, cudaFuncAttributeMaxDynamicSharedMemorySize,
                         2048 * 16 + 64 * 4);

    setup_kernel<<<16, 256>>>(w0, w1, w2);
    pre_kernel<<<782, 256, 2048 * 16 + 64 * 4>>>(h_s, h_d, b0);
    edge_kernel<<<NBLK, ET, SMEM_BYTES>>>(ef, si, ri, b1, b2);
    final_kernel<<<(2 * NN + 255) / 256, 256>>>(h_d, W, out);
}

// round 17
// speedup vs baseline: 4.6375x; 1.0163x over previous
#include <cuda_runtime.h>
#include <cuda_fp16.h>
#include <cstdint>

#define NN 100000
#define NE 800000
#define NBLK 148
#define ET 512          // edge kernel threads (16 warps)

typedef unsigned long long u64;
typedef unsigned int u32;

// scratch (allocation-free rule: __device__ globals)
__device__ float g_agg[NN * 32];
__device__ u32 g_PH[NN * 32];           // fp16x2 fragment-major: [n][q*8 + nt] = (c0,c1)
__device__ u32 g_QH[NN * 32];
__device__ u32 g_HD[NN * 16];           // fp16x2 h_d epilogue-major: [n][q*4 + nt]
__device__ u64 g_B0s[512];              // L0 W0e frags, single fp16 (b0|b1)
__device__ u64 g_B1s[1024];             // L1 W1 frags, single fp16
__device__ u64 g_B2s[512];              // L2 W2 frags, single fp16
__device__ u64 g_BPs[2048];             // precompute weight frags (P|Q), single fp16

// ---------------- packed fp32x2 helpers (final kernel) ----------------
__device__ __forceinline__ u64 pack2(float x) {
    u64 r; asm("mov.b64 %0, {%1, %1};" : "=l"(r) : "f"(x)); return r;
}
__device__ __forceinline__ void ffma2(u64& d, u64 a, u64 b) {
    asm("fma.rn.f32x2 %0, %1, %2, %0;" : "+l"(d) : "l"(a), "l"(b));
}
// rank-1 over 8 outputs (4 u64 acc)
__device__ __forceinline__ void rank1_8(float xf, const float* w8, u64* a0) {
    u64 xa = pack2(xf);
    const ulonglong2* wr = (const ulonglong2*)w8;
#pragma unroll
    for (int j = 0; j < 2; j++) {
        ulonglong2 w = wr[j];
        ffma2(a0[2 * j],     xa, w.x);
        ffma2(a0[2 * j + 1], xa, w.y);
    }
}

// ---------------- fp16 helpers ----------------
__device__ __forceinline__ u32 f16pack(float x0, float x1) {
    u32 r;
    asm("cvt.rn.f16x2.f32 %0, %1, %2;" : "=r"(r) : "f"(x1), "f"(x0));   // low = x0
    return r;
}
__device__ __forceinline__ float2 h2f(u32 v) {
    __half2 h = *(__half2*)&v;
    return __half22float2(h);
}
__device__ __forceinline__ void mma_f16(float c[4], const u32 a[4], u32 b0, u32 b1) {
    asm volatile(
        "mma.sync.aligned.m16n8k16.row.col.f32.f16.f16.f32 "
        "{%0,%1,%2,%3}, {%4,%5,%6,%7}, {%8,%9}, {%0,%1,%2,%3};"
        : "+f"(c[0]), "+f"(c[1]), "+f"(c[2]), "+f"(c[3])
        : "r"(a[0]), "r"(a[1]), "r"(a[2]), "r"(a[3]), "r"(b0), "r"(b1));
}
// 1-term K-chunk: C += A*B, single fp16 B
template <int NTC>
__device__ __forceinline__ void gemm_step1(float C[][4], const u32 a[4],
                                           const u64* sB, int kc, int Kc, int lane) {
    u64 t[NTC];
#pragma unroll
    for (int nt = 0; nt < NTC; nt++) t[nt] = sB[(nt * Kc + kc) * 32 + lane];
#pragma unroll
    for (int nt = 0; nt < NTC; nt++) mma_f16(C[nt], a, (u32)t[nt], (u32)(t[nt] >> 32));
}
__device__ __forceinline__ void build_a(const float cA[4], const float cB[4], u32 a[4]) {
    a[0] = f16pack(fmaxf(cA[0], 0.f), fmaxf(cA[1], 0.f));
    a[1] = f16pack(fmaxf(cA[2], 0.f), fmaxf(cA[3], 0.f));
    a[2] = f16pack(fmaxf(cB[0], 0.f), fmaxf(cB[1], 0.f));
    a[3] = f16pack(fmaxf(cB[2], 0.f), fmaxf(cB[3], 0.f));
}
__device__ __forceinline__ void red2(float* p, float x, float y) {
    asm volatile("red.global.add.v2.f32 [%0], {%1,%2};" :: "l"(p), "f"(x), "f"(y));
}

// ---------------- setup ----------------
// i<512: B0s; [512,1536): B1s; [1536,2048): B2s; [2048,4096): BPs (P|Q, 64 slots).
__global__ void setup_kernel(const float* __restrict__ w0, const float* __restrict__ w1,
                             const float* __restrict__ w2) {
    int i = blockIdx.x * 256 + threadIdx.x;
    if (i >= 4096) return;
    int lane = i & 31;
    int g = lane >> 2, q = lane & 3;
    if (i < 512) {
        int f = i >> 5;                   // 0..15: nt = f>>1, kc = f&1
        int nt = f >> 1, kc = f & 1;
        int n = nt * 8 + g, k0 = 16 * kc + 2 * q;
        const float* W = w0 + 128 * 64;   // W0e, stride 64
        u32 b0 = f16pack(W[(size_t)k0 * 64 + n],       W[(size_t)(k0 + 1) * 64 + n]);
        u32 b1 = f16pack(W[(size_t)(k0 + 8) * 64 + n], W[(size_t)(k0 + 9) * 64 + n]);
        g_B0s[i] = (u64)b0 | ((u64)b1 << 32);
    } else if (i < 1536) {
        int j = i - 512;
        int f = j >> 5;                   // 0..31: nt = f>>2, kc = f&3
        int nt = f >> 2, kc = f & 3;
        int n = nt * 8 + g, k0 = 16 * kc + 2 * q;
        u32 b0 = f16pack(w1[(size_t)k0 * 64 + n],       w1[(size_t)(k0 + 1) * 64 + n]);
        u32 b1 = f16pack(w1[(size_t)(k0 + 8) * 64 + n], w1[(size_t)(k0 + 9) * 64 + n]);
        g_B1s[j] = (u64)b0 | ((u64)b1 << 32);
    } else if (i < 2048) {
        int j = i - 1536;
        int f = j >> 5;                   // 0..15: nt = f>>2, kc = f&3
        int nt = f >> 2, kc = f & 3;
        int n = nt * 8 + g, k0 = 16 * kc + 2 * q;
        u32 b0 = f16pack(w2[(size_t)k0 * 32 + n],       w2[(size_t)(k0 + 1) * 32 + n]);
        u32 b1 = f16pack(w2[(size_t)(k0 + 8) * 32 + n], w2[(size_t)(k0 + 9) * 32 + n]);
        g_B2s[j] = (u64)b0 | ((u64)b1 << 32);
    } else {
        // BPs: 64 slots (nt 0..15 = P rows 0..7 | Q rows 8..15; kc 0..3) over W0 rows
        int j = i - 2048;
        int ff = j >> 5;
        int nt = ff >> 2, kc = ff & 3;
        int isq = (nt >= 8) ? 32 : 0;
        int nidx = (nt & 7) * 8 + g;
        int k0 = 16 * kc + 2 * q;
        int r00 = ((k0     < 32) ? k0     : k0 + 32) + isq;
        int r01 = ((k0 + 1 < 32) ? k0 + 1 : k0 + 33) + isq;
        int r10 = ((k0 + 8 < 32) ? k0 + 8 : k0 + 40) + isq;
        int r11 = ((k0 + 9 < 32) ? k0 + 9 : k0 + 41) + isq;
        u32 b0 = f16pack(w0[(size_t)r00 * 64 + nidx], w0[(size_t)r01 * 64 + nidx]);
        u32 b1 = f16pack(w0[(size_t)r10 * 64 + nidx], w0[(size_t)r11 * 64 + nidx]);
        g_BPs[j] = (u64)b0 | ((u64)b1 << 32);
    }
}

// ---------------- precompute: P|Q tables via fp16 1-term MMA; h_d table; zeros g_agg ----------------
__global__ void __launch_bounds__(256, 1)
pre_kernel(const float* __restrict__ h_s, const float* __restrict__ h_d,
           const float* __restrict__ b0) {
    extern __shared__ u64 smem_u8[];
    float* s_b0 = (float*)(smem_u8 + 2048);
    const int tid = threadIdx.x, wid = tid >> 5, lane = tid & 31;
    const int g = lane >> 2, q = lane & 3;
    for (int i = tid; i < 2048; i += 256) smem_u8[i] = g_BPs[i];
    if (tid < 64) s_b0[tid] = b0[tid];
    __syncthreads();

    int n0 = (blockIdx.x * 8 + wid) * 16;
    if (n0 >= NN) return;

    float C[16][4];
#pragma unroll
    for (int nt = 0; nt < 8; nt++) {
        C[nt][0] = 0.f; C[nt][1] = 0.f; C[nt][2] = 0.f; C[nt][3] = 0.f;
        float b0v = s_b0[nt * 8 + 2 * q], b1v = s_b0[nt * 8 + 2 * q + 1];
        C[8 + nt][0] = b0v; C[8 + nt][1] = b1v; C[8 + nt][2] = b0v; C[8 + nt][3] = b1v;
    }
#pragma unroll
    for (int kc = 0; kc < 4; kc++) {
        const float* src = (kc < 2) ? h_s : h_d;
        int off = (kc & 1) * 16 + 2 * q;
        float2 x0 = *(const float2*)(src + (size_t)(n0 + g) * 32 + off);
        float2 x1 = *(const float2*)(src + (size_t)(n0 + 8 + g) * 32 + off);
        float2 x2 = *(const float2*)(src + (size_t)(n0 + g) * 32 + off + 8);
        float2 x3 = *(const float2*)(src + (size_t)(n0 + 8 + g) * 32 + off + 8);
        u32 a[4];
        a[0] = f16pack(x0.x, x0.y);
        a[1] = f16pack(x1.x, x1.y);
        a[2] = f16pack(x2.x, x2.y);
        a[3] = f16pack(x3.x, x3.y);
        gemm_step1<8>(C,     a, smem_u8,           kc, 4, lane);   // P (slots 0..31)
        gemm_step1<8>(C + 8, a, smem_u8 + 32 * 32, kc, 4, lane);   // Q (slots 32..63)
    }
    // pack P/Q to fp16x2, store fragment-major [n][q*8 + nt]
    {
        u32 vp0[8], vp1[8], vq0[8], vq1[8];
#pragma unroll
        for (int nt = 0; nt < 8; nt++) {
            vp0[nt] = f16pack(C[nt][0], C[nt][1]);
            vp1[nt] = f16pack(C[nt][2], C[nt][3]);
            vq0[nt] = f16pack(C[8+nt][0], C[8+nt][1]);
            vq1[nt] = f16pack(C[8+nt][2], C[8+nt][3]);
        }
        uint4* p = (uint4*)(g_PH + (size_t)(n0 + g) * 32 + q * 8);
        p[0] = make_uint4(vp0[0], vp0[1], vp0[2], vp0[3]);
        p[1] = make_uint4(vp0[4], vp0[5], vp0[6], vp0[7]);
        p = (uint4*)(g_PH + (size_t)(n0 + 8 + g) * 32 + q * 8);
        p[0] = make_uint4(vp1[0], vp1[1], vp1[2], vp1[3]);
        p[1] = make_uint4(vp1[4], vp1[5], vp1[6], vp1[7]);
        p = (uint4*)(g_QH + (size_t)(n0 + g) * 32 + q * 8);
        p[0] = make_uint4(vq0[0], vq0[1], vq0[2], vq0[3]);
        p[1] = make_uint4(vq0[4], vq0[5], vq0[6], vq0[7]);
        p = (uint4*)(g_QH + (size_t)(n0 + 8 + g) * 32 + q * 8);
        p[0] = make_uint4(vq1[0], vq1[1], vq1[2], vq1[3]);
        p[1] = make_uint4(vq1[4], vq1[5], vq1[6], vq1[7]);
    }
    // h_d fp16 epilogue table: [n][q*4 + nt] = cols (nt*8+2q, +1)
    {
#pragma unroll
        for (int rsel = 0; rsel < 2; rsel++) {
            int n = n0 + rsel * 8 + g;
            u32 v[4];
#pragma unroll
            for (int nt = 0; nt < 4; nt++) {
                float2 x = *(const float2*)(h_d + (size_t)n * 32 + nt * 8 + 2 * q);
                v[nt] = f16pack(x.x, x.y);
            }
            *(uint4*)(g_HD + (size_t)n * 16 + q * 4) = make_uint4(v[0], v[1], v[2], v[3]);
        }
    }
    float4 z = make_float4(0.f, 0.f, 0.f, 0.f);
    float4* ag = (float4*)(g_agg + (size_t)n0 * 32);
#pragma unroll
    for (int i = 0; i < 4; i++) ag[lane + 32 * i] = z;
}

// ---------------- edge kernel: fp16 1-term MMA MLP, all-fp16 gathers ----------------
// smem: sB0s u64[512] @0 (4KB), sB1s u64[1024] @4096 (8KB), sB2s u64[512] @12288 (4KB),
//       biases @16384
#define SMEM_BYTES (16384 + 96 * 4)

__global__ void __launch_bounds__(ET, 1)
edge_kernel(const float* __restrict__ ef,
            const int* __restrict__ si, const int* __restrict__ ri,
            const float* __restrict__ b1, const float* __restrict__ b2) {
    extern __shared__ char smem_c[];
    u64* sB0s = (u64*)smem_c;
    u64* sB1s = (u64*)(smem_c + 4096);
    u64* sB2s = (u64*)(smem_c + 12288);
    float* s_b1 = (float*)(smem_c + 16384);
    float* s_b2 = s_b1 + 64;

    const int tid = threadIdx.x, wid = tid >> 5, lane = tid & 31;
    for (int i = tid; i < 512; i += ET) sB0s[i] = g_B0s[i];
    for (int i = tid; i < 1024; i += ET) sB1s[i] = g_B1s[i];
    for (int i = tid; i < 512; i += ET) sB2s[i] = g_B2s[i];
    if (tid < 64) s_b1[tid] = b1[tid];
    if (tid < 32) s_b2[tid] = b2[tid];
    __syncthreads();

    const int g = lane >> 2, q = lane & 3;
    const int col2 = 2 * q;
    const int WPC = ET / 32;

#pragma unroll 1
    for (int base = blockIdx.x * (WPC * 16) + wid * 16; base < NE; base += NBLK * (WPC * 16)) {
        int e0 = base + g, e1 = base + 8 + g;
        bool v0 = e0 < NE, v1 = e1 < NE;
        int e0c = v0 ? e0 : NE - 1;
        int e1c = v1 ? e1 : NE - 1;
        int s0 = si[e0c], rc0 = ri[e0c];
        int s1 = si[e1c], rc1 = ri[e1c];

        // ===== layer 0: C init from P[s]+Q[r] (fp16x2 gathers, fp32 adds) =====
        float C[8][4];
        {
            const uint4* P0 = (const uint4*)(g_PH + (size_t)s0  * 32 + q * 8);
            const uint4* Q0 = (const uint4*)(g_QH + (size_t)rc0 * 32 + q * 8);
            const uint4* P1 = (const uint4*)(g_PH + (size_t)s1  * 32 + q * 8);
            const uint4* Q1 = (const uint4*)(g_QH + (size_t)rc1 * 32 + q * 8);
            uint4 pa0 = P0[0], pa1 = P0[1], qa0 = Q0[0], qa1 = Q0[1];
            uint4 pb0 = P1[0], pb1 = P1[1], qb0 = Q1[0], qb1 = Q1[1];
            u32 pv0[8] = {pa0.x, pa0.y, pa0.z, pa0.w, pa1.x, pa1.y, pa1.z, pa1.w};
            u32 qv0[8] = {qa0.x, qa0.y, qa0.z, qa0.w, qa1.x, qa1.y, qa1.z, qa1.w};
            u32 pv1[8] = {pb0.x, pb0.y, pb0.z, pb0.w, pb1.x, pb1.y, pb1.z, pb1.w};
            u32 qv1[8] = {qb0.x, qb0.y, qb0.z, qb0.w, qb1.x, qb1.y, qb1.z, qb1.w};
#pragma unroll
            for (int nt = 0; nt < 8; nt++) {
                float2 a = h2f(pv0[nt]), b = h2f(qv0[nt]);
                C[nt][0] = a.x + b.x; C[nt][1] = a.y + b.y;
                a = h2f(pv1[nt]); b = h2f(qv1[nt]);
                C[nt][2] = a.x + b.x; C[nt][3] = a.y + b.y;
            }
        }
        // ===== layer 0: += ef @ W0e (1-term) =====
#pragma unroll
        for (int kc = 0; kc < 2; kc++) {
            int off = 16 * kc + col2;
            float2 x0 = *(const float2*)(ef + (size_t)e0c * 32 + off);
            float2 x1 = *(const float2*)(ef + (size_t)e1c * 32 + off);
            float2 x2 = *(const float2*)(ef + (size_t)e0c * 32 + off + 8);
            float2 x3 = *(const float2*)(ef + (size_t)e1c * 32 + off + 8);
            u32 a[4];
            a[0] = f16pack(x0.x, x0.y);
            a[1] = f16pack(x1.x, x1.y);
            a[2] = f16pack(x2.x, x2.y);
            a[3] = f16pack(x3.x, x3.y);
            gemm_step1<8>(C, a, sB0s, kc, 2, lane);
        }

        // ===== layer 1 (1-term) =====
        float C1[8][4];
#pragma unroll
        for (int nt = 0; nt < 8; nt++) {
            float bb0 = s_b1[nt * 8 + col2], bb1 = s_b1[nt * 8 + col2 + 1];
            C1[nt][0] = bb0; C1[nt][1] = bb1; C1[nt][2] = bb0; C1[nt][3] = bb1;
        }
#pragma unroll
        for (int kc = 0; kc < 4; kc++) {
            u32 a[4];
            build_a(C[2 * kc], C[2 * kc + 1], a);
            gemm_step1<8>(C1, a, sB1s, kc, 4, lane);
        }

        // ===== layer 2 (1-term) =====
        float C2[4][4];
#pragma unroll
        for (int nt = 0; nt < 4; nt++) {
            float bb0 = s_b2[nt * 8 + col2], bb1 = s_b2[nt * 8 + col2 + 1];
            C2[nt][0] = bb0; C2[nt][1] = bb1; C2[nt][2] = bb0; C2[nt][3] = bb1;
        }
#pragma unroll
        for (int kc = 0; kc < 4; kc++) {
            u32 a[4];
            build_a(C1[2 * kc], C1[2 * kc + 1], a);
            gemm_step1<4>(C2, a, sB2s, kc, 4, lane);
        }

        // ===== epilogue: relu(psi) * (h_dj - h_di), fp16 h_d gathers =====
        {
            uint4 dj0 = *(const uint4*)(g_HD + (size_t)rc0 * 16 + q * 4);
            uint4 di0 = *(const uint4*)(g_HD + (size_t)s0  * 16 + q * 4);
            uint4 dj1 = *(const uint4*)(g_HD + (size_t)rc1 * 16 + q * 4);
            uint4 di1 = *(const uint4*)(g_HD + (size_t)s1  * 16 + q * 4);
            u32 j0[4] = {dj0.x, dj0.y, dj0.z, dj0.w};
            u32 i0[4] = {di0.x, di0.y, di0.z, di0.w};
            u32 j1[4] = {dj1.x, dj1.y, dj1.z, dj1.w};
            u32 i1[4] = {di1.x, di1.y, di1.z, di1.w};
#pragma unroll
            for (int nt = 0; nt < 4; nt++) {
                int cc = nt * 8 + col2;
                if (v0) {
                    float2 a = h2f(j0[nt]), b = h2f(i0[nt]);
                    red2(g_agg + (size_t)rc0 * 32 + cc,
                         fmaxf(C2[nt][0], 0.f) * (a.x - b.x),
                         fmaxf(C2[nt][1], 0.f) * (a.y - b.y));
                }
                if (v1) {
                    float2 a = h2f(j1[nt]), b = h2f(i1[nt]);
                    red2(g_agg + (size_t)rc1 * 32 + cc,
                         fmaxf(C2[nt][2], 0.f) * (a.x - b.x),
                         fmaxf(C2[nt][3], 0.f) * (a.y - b.y));
                }
            }
        }
    }
}

// out[n] = h_d_prev[n] + agg[n] @ W   (4 threads per node, 8 outputs each)
__global__ void __launch_bounds__(256)
final_kernel(const float* __restrict__ h_d, const float* __restrict__ W,
             float* __restrict__ out) {
    __shared__ float sW[1024];
    int tid = threadIdx.x;
    {
        float4* d4 = (float4*)sW;
        const float4* s4 = (const float4*)W;
        for (int i = tid; i < 256; i += 256) d4[i] = s4[i];
    }
    __syncthreads();
    int idx = blockIdx.x * 256 + tid;
    int n = idx >> 2, qtr = idx & 3;
    if (n >= NN) return;

    u64 acc[4];
    {
        const ulonglong2* hp = (const ulonglong2*)(h_d + (size_t)n * 32 + qtr * 8);
#pragma unroll
        for (int j = 0; j < 2; j++) {
            ulonglong2 t = hp[j];
            acc[2 * j] = t.x; acc[2 * j + 1] = t.y;
        }
    }
    const float4* ap = (const float4*)(g_agg + (size_t)n * 32);
    const float* wb = sW + qtr * 8;
#pragma unroll
    for (int i = 0; i < 8; i++) {
        float4 a = ap[i];
        rank1_8(a.x, wb + (4 * i) * 32,     acc);
        rank1_8(a.y, wb + (4 * i + 1) * 32, acc);
        rank1_8(a.z, wb + (4 * i + 2) * 32, acc);
        rank1_8(a.w, wb + (4 * i + 3) * 32, acc);
    }
    ulonglong2* op = (ulonglong2*)(out + (size_t)n * 32 + qtr * 8);
#pragma unroll
    for (int j = 0; j < 2; j++) {
        ulonglong2 t; t.x = acc[2 * j]; t.y = acc[2 * j + 1];
        op[j] = t;
    }
}

extern "C" void kernel_launch(void* const* d_in, const int* in_sizes, int n_in,
                              void* d_out, int out_size) {
    const float* h_d = (const float*)d_in[0];
    const float* h_s = (const float*)d_in[1];
    const float* ef  = (const float*)d_in[2];
    const int*   si  = (const int*)d_in[3];
    const int*   ri  = (const int*)d_in[4];
    const float* w0  = (const float*)d_in[5];
    const float* b0  = (const float*)d_in[6];
    const float* w1  = (const float*)d_in[7];
    const float* b1  = (const float*)d_in[8];
    const float* w2  = (const float*)d_in[9];
    const float* b2  = (const float*)d_in[10];
    const float* W   = (const float*)d_in[11];
    float* out = (float*)d_out;

    cudaFuncSetAttribute(edge_kernel, cudaFuncAttributeMaxDynamicSharedMemorySize,
                         SMEM_BYTES);
    cudaFuncSetAttribute(pre_kernel, cudaFuncAttributeMaxDynamicSharedMemorySize,
                         2048 * 8 + 64 * 4);

    setup_kernel<<<16, 256>>>(w0, w1, w2);
    pre_kernel<<<782, 256, 2048 * 8 + 64 * 4>>>(h_s, h_d, b0);
    edge_kernel<<<NBLK, ET, SMEM_BYTES>>>(ef, si, ri, b1, b2);
    final_kernel<<<(4 * NN + 255) / 256, 256>>>(h_d, W, out);
}